// round 1
// baseline (speedup 1.0000x reference)
#include <cuda_runtime.h>
#include <math.h>

// Problem constants
constexpr int BATCH  = 2;
constexpr int SEQ    = 2048;
constexpr int EMB    = 2048;
constexpr int NHEADS = 16;
constexpr int NKVH   = 4;
constexpr int HDIM   = 128;
constexpr int WIN    = 1024;           // S/2
constexpr int GQA    = NHEADS / NKVH;  // 4

// Scratch (device globals: no allocations allowed)
__device__ __align__(16) float g_Q [BATCH * SEQ * NHEADS * HDIM];  // 8.39M
__device__ __align__(16) float g_K [BATCH * SEQ * NKVH   * HDIM];  // 2.10M
__device__ __align__(16) float g_V [BATCH * SEQ * NKVH   * HDIM];  // 2.10M
__device__ __align__(16) float g_AO[BATCH * SEQ * EMB];            // 8.39M

// ---------------------------------------------------------------------------
// SGEMM NT: C[M,N] = A[M,K] * B[N,K]^T   (all row-major, M%128==0, N%128==0, K%8==0)
// 128x128 block tile, BK=8, 256 threads, 8x8 per thread.
// ---------------------------------------------------------------------------
__global__ __launch_bounds__(256) void sgemm_nt(
    const float* __restrict__ A, const float* __restrict__ Bm,
    float* __restrict__ C, int M, int N, int K)
{
    constexpr int BM = 128, BN = 128, BK = 8, TM = 8, TN = 8;
    __shared__ float As[BK][BM];
    __shared__ float Bs[BK][BN];

    const int tid = threadIdx.x;
    const int m0 = blockIdx.y * BM;
    const int n0 = blockIdx.x * BN;

    const int lr = tid >> 1;          // 0..127: row within tile for loads
    const int lk = (tid & 1) * 4;     // 0 or 4: k offset for loads

    const int rm = (tid >> 4) * TM;   // compute rows 0..120
    const int rn = (tid & 15) * TN;   // compute cols 0..120

    const float* Aptr = A  + (m0 + lr) * K + lk;
    const float* Bptr = Bm + (n0 + lr) * K + lk;

    float c[TM][TN];
#pragma unroll
    for (int i = 0; i < TM; ++i)
#pragma unroll
        for (int j = 0; j < TN; ++j) c[i][j] = 0.f;

    float ar[TM], br[TN];

    for (int kt = 0; kt < K; kt += BK) {
        float4 av = *reinterpret_cast<const float4*>(Aptr + kt);
        float4 bv = *reinterpret_cast<const float4*>(Bptr + kt);
        __syncthreads();   // previous tile fully consumed
        As[lk + 0][lr] = av.x; As[lk + 1][lr] = av.y;
        As[lk + 2][lr] = av.z; As[lk + 3][lr] = av.w;
        Bs[lk + 0][lr] = bv.x; Bs[lk + 1][lr] = bv.y;
        Bs[lk + 2][lr] = bv.z; Bs[lk + 3][lr] = bv.w;
        __syncthreads();
#pragma unroll
        for (int kk = 0; kk < BK; ++kk) {
            *reinterpret_cast<float4*>(&ar[0]) = *reinterpret_cast<const float4*>(&As[kk][rm]);
            *reinterpret_cast<float4*>(&ar[4]) = *reinterpret_cast<const float4*>(&As[kk][rm + 4]);
            *reinterpret_cast<float4*>(&br[0]) = *reinterpret_cast<const float4*>(&Bs[kk][rn]);
            *reinterpret_cast<float4*>(&br[4]) = *reinterpret_cast<const float4*>(&Bs[kk][rn + 4]);
#pragma unroll
            for (int i = 0; i < TM; ++i)
#pragma unroll
                for (int j = 0; j < TN; ++j)
                    c[i][j] += ar[i] * br[j];
        }
    }

#pragma unroll
    for (int i = 0; i < TM; ++i) {
        float4 v0 = make_float4(c[i][0], c[i][1], c[i][2], c[i][3]);
        float4 v1 = make_float4(c[i][4], c[i][5], c[i][6], c[i][7]);
        float* cp = C + (m0 + rm + i) * N + n0 + rn;
        *reinterpret_cast<float4*>(cp)     = v0;
        *reinterpret_cast<float4*>(cp + 4) = v1;
    }
}

// ---------------------------------------------------------------------------
// RoPE: in-place on g_Q (NH heads) and g_K (NKV heads).
// duplicated-half layout: out[d]    = x[d]*cos[d]    - x[d+64]*sin[d]
//                         out[d+64] = x[d+64]*cos[d+64] + x[d]*sin[d+64]
// ---------------------------------------------------------------------------
__global__ void rope_kernel(const float* __restrict__ cosb,
                            const float* __restrict__ sinb)
{
    const int total = BATCH * SEQ * (NHEADS + NKVH) * (HDIM / 2);
    int idx = blockIdx.x * blockDim.x + threadIdx.x;
    if (idx >= total) return;
    int d    = idx & 63;
    int rest = idx >> 6;
    int slot = rest % (NHEADS + NKVH);
    int bs   = rest / (NHEADS + NKVH);       // b*SEQ + s
    int s    = bs % SEQ;

    float c0 = cosb[s * HDIM + d];
    float c1 = cosb[s * HDIM + d + 64];
    float s0 = sinb[s * HDIM + d];
    float s1 = sinb[s * HDIM + d + 64];

    float* p;
    if (slot < NHEADS) p = g_Q + (bs * NHEADS + slot) * HDIM;
    else               p = g_K + (bs * NKVH + (slot - NHEADS)) * HDIM;

    float x0 = p[d], x1 = p[d + 64];
    p[d]      = x0 * c0 - x1 * s0;
    p[d + 64] = x1 * c1 + x0 * s1;
}

// ---------------------------------------------------------------------------
// Sliding-window GQA flash attention.
// Block: 64 query rows of one (b, h). 128 threads: thread t -> row t/2,
// half-dims (t&1)*64. 32-key tiles staged in static smem.
// ---------------------------------------------------------------------------
__global__ __launch_bounds__(128) void attn_kernel()
{
    constexpr int KT = 32;
    __shared__ float Ks[KT * HDIM];   // 16 KB
    __shared__ float Vs[KT * HDIM];   // 16 KB

    const int t    = threadIdx.x;
    const int r    = t >> 1;
    const int half = t & 1;
    const int q0   = blockIdx.x * 64;
    const int h    = blockIdx.y;
    const int b    = blockIdx.z;
    const int kvh  = h / GQA;
    const int q_idx = q0 + r;
    const int bS = b * SEQ;

    const float scale = 0.08838834764831845f;   // 1/sqrt(128)

    // Q row (pre-scaled)
    float qreg[64];
    {
        const float4* qp = reinterpret_cast<const float4*>(
            g_Q + ((bS + q_idx) * NHEADS + h) * HDIM + half * 64);
#pragma unroll
        for (int i = 0; i < 16; ++i) {
            float4 v = qp[i];
            qreg[4 * i + 0] = v.x * scale;
            qreg[4 * i + 1] = v.y * scale;
            qreg[4 * i + 2] = v.z * scale;
            qreg[4 * i + 3] = v.w * scale;
        }
    }

    float acc[64];
#pragma unroll
    for (int i = 0; i < 64; ++i) acc[i] = 0.f;
    float m_run = -1e30f, l_run = 0.f;

    const unsigned pmask = 3u << ((t & 31) & ~1);   // the two lanes of this row-pair

    const float4* K4 = reinterpret_cast<const float4*>(g_K);
    const float4* V4 = reinterpret_cast<const float4*>(g_V);

    int jstart = q0 - (WIN - 1);
    if (jstart < 0) jstart = 0;
    jstart &= ~(KT - 1);

    for (int j0 = jstart; j0 < q0 + 64; j0 += KT) {
        __syncthreads();
        // stage K/V tile (KT*32 float4 per tensor, 128 threads -> 8 each)
#pragma unroll
        for (int i = t; i < KT * 32; i += 128) {
            int j  = i >> 5;
            int d4 = i & 31;
            int gi = ((bS + j0 + j) * NKVH + kvh) * 32 + d4;
            reinterpret_cast<float4*>(Ks)[i] = K4[gi];
            reinterpret_cast<float4*>(Vs)[i] = V4[gi];
        }
        __syncthreads();

        // per-row tile skip (both lanes of a pair agree)
        bool active = (j0 <= q_idx) && (q_idx - (j0 + KT - 1) < WIN);
        if (active) {
            float sreg[KT];
            float tmax = -1e30f;
#pragma unroll
            for (int j = 0; j < KT; ++j) {
                const float4* kp = reinterpret_cast<const float4*>(Ks + j * HDIM + half * 64);
                float p = 0.f;
#pragma unroll
                for (int dd = 0; dd < 16; ++dd) {
                    float4 kv = kp[dd];
                    p += qreg[4 * dd + 0] * kv.x + qreg[4 * dd + 1] * kv.y
                       + qreg[4 * dd + 2] * kv.z + qreg[4 * dd + 3] * kv.w;
                }
                p += __shfl_xor_sync(pmask, p, 1);
                int dist = q_idx - (j0 + j);
                sreg[j] = (dist >= 0 && dist < WIN) ? p : -1e30f;
                tmax = fmaxf(tmax, sreg[j]);
            }
            float mnew = fmaxf(m_run, tmax);
            float corr = __expf(m_run - mnew);
            l_run *= corr;
#pragma unroll
            for (int dd = 0; dd < 64; ++dd) acc[dd] *= corr;
#pragma unroll
            for (int j = 0; j < KT; ++j) {
                float p = __expf(sreg[j] - mnew);
                l_run += p;
                const float4* vp = reinterpret_cast<const float4*>(Vs + j * HDIM + half * 64);
#pragma unroll
                for (int dd = 0; dd < 16; ++dd) {
                    float4 vv = vp[dd];
                    acc[4 * dd + 0] += p * vv.x;
                    acc[4 * dd + 1] += p * vv.y;
                    acc[4 * dd + 2] += p * vv.z;
                    acc[4 * dd + 3] += p * vv.w;
                }
            }
            m_run = mnew;
        }
    }

    float inv = 1.f / l_run;
    float4* op = reinterpret_cast<float4*>(
        g_AO + ((bS + q_idx) * NHEADS + h) * HDIM + half * 64);
#pragma unroll
    for (int i = 0; i < 16; ++i) {
        op[i] = make_float4(acc[4 * i + 0] * inv, acc[4 * i + 1] * inv,
                            acc[4 * i + 2] * inv, acc[4 * i + 3] * inv);
    }
}

// ---------------------------------------------------------------------------
// Launch
// ---------------------------------------------------------------------------
extern "C" void kernel_launch(void* const* d_in, const int* in_sizes, int n_in,
                              void* d_out, int out_size)
{
    const float* x    = (const float*)d_in[0];
    const float* cosb = (const float*)d_in[1];
    const float* sinb = (const float*)d_in[2];
    const float* Wq   = (const float*)d_in[3];
    const float* Wk   = (const float*)d_in[4];
    const float* Wv   = (const float*)d_in[5];
    const float* Wo   = (const float*)d_in[6];
    float* out = (float*)d_out;

    float *Q, *K, *V, *AO;
    cudaGetSymbolAddress((void**)&Q,  g_Q);
    cudaGetSymbolAddress((void**)&K,  g_K);
    cudaGetSymbolAddress((void**)&V,  g_V);
    cudaGetSymbolAddress((void**)&AO, g_AO);

    const int M = BATCH * SEQ;   // 4096

    // QKV projections
    sgemm_nt<<<dim3(EMB / 128, M / 128), 256>>>(x, Wq, Q, M, NHEADS * HDIM, EMB);
    sgemm_nt<<<dim3((NKVH * HDIM) / 128, M / 128), 256>>>(x, Wk, K, M, NKVH * HDIM, EMB);
    sgemm_nt<<<dim3((NKVH * HDIM) / 128, M / 128), 256>>>(x, Wv, V, M, NKVH * HDIM, EMB);

    // RoPE on Q and K
    {
        int total = BATCH * SEQ * (NHEADS + NKVH) * (HDIM / 2);
        rope_kernel<<<(total + 255) / 256, 256>>>(cosb, sinb);
    }

    // Attention
    attn_kernel<<<dim3(SEQ / 64, NHEADS, BATCH), 128>>>();

    // Output projection
    sgemm_nt<<<dim3(EMB / 128, M / 128), 256>>>(AO, Wo, out, M, EMB, EMB);
}

// round 3
// speedup vs baseline: 1.5851x; 1.5851x over previous
#include <cuda_runtime.h>
#include <cstdint>
#include <math.h>

// Problem constants
constexpr int BATCH  = 2;
constexpr int SEQ    = 2048;
constexpr int EMB    = 2048;
constexpr int NHEADS = 16;
constexpr int NKVH   = 4;
constexpr int HDIM   = 128;
constexpr int WIN    = 1024;           // S/2
constexpr int GQA    = NHEADS / NKVH;  // 4

// Scratch (device globals: no allocations allowed)
__device__ __align__(16) float g_Q [BATCH * SEQ * NHEADS * HDIM];
__device__ __align__(16) float g_K [BATCH * SEQ * NKVH   * HDIM];
__device__ __align__(16) float g_V [BATCH * SEQ * NKVH   * HDIM];
__device__ __align__(16) float g_AO[BATCH * SEQ * EMB];

// ===========================================================================
// TF32 mma.sync GEMM (NT): C[M,N] = A[M,K] * B[N,K]^T, all row-major.
// 128x128x32 CTA tile, 256 threads, 8 warps (2x4), warp tile 64x32,
// mma.m16n8k8.tf32, double-buffered smem, register prefetch pipeline.
// ===========================================================================

constexpr int BM = 128, BN = 128, BKC = 32;
constexpr int SAPAD = 36;                     // padded row stride (floats)
constexpr int TILE_FLOATS = BM * SAPAD;       // 4608 floats per operand tile
constexpr int SMEM_GEMM = 2 * 2 * TILE_FLOATS * 4;   // 73728 bytes

__device__ __forceinline__ uint32_t f2tf32(float x) {
    uint32_t r;
    asm("cvt.rna.tf32.f32 %0, %1;" : "=r"(r) : "f"(x));
    return r;
}

__device__ __forceinline__ void mma_tf32(
    float& d0, float& d1, float& d2, float& d3,
    uint32_t a0, uint32_t a1, uint32_t a2, uint32_t a3,
    uint32_t b0, uint32_t b1)
{
    asm volatile(
        "mma.sync.aligned.m16n8k8.row.col.f32.tf32.tf32.f32 "
        "{%0,%1,%2,%3}, {%4,%5,%6,%7}, {%8,%9}, {%0,%1,%2,%3};"
        : "+f"(d0), "+f"(d1), "+f"(d2), "+f"(d3)
        : "r"(a0), "r"(a1), "r"(a2), "r"(a3), "r"(b0), "r"(b1));
}

__global__ __launch_bounds__(256) void gemm_mma(
    const float* __restrict__ A, const float* __restrict__ B,
    float* __restrict__ C, int M, int N, int K)
{
    extern __shared__ uint32_t smem[];   // [2 stages][A tile | B tile]

    const int tid  = threadIdx.x;
    const int lane = tid & 31;
    const int wid  = tid >> 5;
    const int m0 = blockIdx.y * BM;
    const int n0 = blockIdx.x * BN;

    const int wm  = (wid >> 2) * 64;    // warp M offset in tile
    const int wn  = (wid & 3) * 32;     // warp N offset in tile
    const int gID = lane >> 2;          // 0..7
    const int tig = lane & 3;           // 0..3

    // gmem->reg load mapping: element i = tid + 256*j covers 128 rows x 8 float4
    const int lr0 = tid >> 3;           // row base (+32 per j)
    const int lc4 = tid & 7;            // float4 column

    const float* Abase = A + (size_t)(m0 + lr0) * K + lc4 * 4;
    const float* Bbase = B + (size_t)(n0 + lr0) * K + lc4 * 4;

    float acc[4][4][4];
#pragma unroll
    for (int mi = 0; mi < 4; ++mi)
#pragma unroll
        for (int ni = 0; ni < 4; ++ni)
#pragma unroll
            for (int q = 0; q < 4; ++q) acc[mi][ni][q] = 0.f;

    uint4 pa[4], pb[4];
    const int nch = K / BKC;            // 64 for K=2048

    // ---- load chunk 0 ----
#pragma unroll
    for (int j = 0; j < 4; ++j) {
        float4 av = *reinterpret_cast<const float4*>(Abase + (size_t)(32 * j) * K);
        float4 bv = *reinterpret_cast<const float4*>(Bbase + (size_t)(32 * j) * K);
        pa[j] = make_uint4(f2tf32(av.x), f2tf32(av.y), f2tf32(av.z), f2tf32(av.w));
        pb[j] = make_uint4(f2tf32(bv.x), f2tf32(bv.y), f2tf32(bv.z), f2tf32(bv.w));
    }
#pragma unroll
    for (int j = 0; j < 4; ++j) {
        int r = lr0 + 32 * j;
        *reinterpret_cast<uint4*>(&smem[r * SAPAD + lc4 * 4]) = pa[j];
        *reinterpret_cast<uint4*>(&smem[TILE_FLOATS + r * SAPAD + lc4 * 4]) = pb[j];
    }
    __syncthreads();

    for (int c = 0; c < nch; ++c) {
        // prefetch next chunk into regs
        if (c + 1 < nch) {
            const int kb = (c + 1) * BKC;
#pragma unroll
            for (int j = 0; j < 4; ++j) {
                float4 av = *reinterpret_cast<const float4*>(Abase + (size_t)(32 * j) * K + kb);
                float4 bv = *reinterpret_cast<const float4*>(Bbase + (size_t)(32 * j) * K + kb);
                pa[j] = make_uint4(f2tf32(av.x), f2tf32(av.y), f2tf32(av.z), f2tf32(av.w));
                pb[j] = make_uint4(f2tf32(bv.x), f2tf32(bv.y), f2tf32(bv.z), f2tf32(bv.w));
            }
        }

        // compute from stage c&1
        const uint32_t* sA = smem + (c & 1) * 2 * TILE_FLOATS;
        const uint32_t* sB = sA + TILE_FLOATS;
#pragma unroll
        for (int ks = 0; ks < 4; ++ks) {
            const int kq = ks * 8;
            uint32_t af[4][4], bf[4][2];
#pragma unroll
            for (int mi = 0; mi < 4; ++mi) {
                int row = wm + mi * 16 + gID;
                af[mi][0] = sA[row * SAPAD + kq + tig];
                af[mi][1] = sA[(row + 8) * SAPAD + kq + tig];
                af[mi][2] = sA[row * SAPAD + kq + tig + 4];
                af[mi][3] = sA[(row + 8) * SAPAD + kq + tig + 4];
            }
#pragma unroll
            for (int ni = 0; ni < 4; ++ni) {
                int col = wn + ni * 8 + gID;
                bf[ni][0] = sB[col * SAPAD + kq + tig];
                bf[ni][1] = sB[col * SAPAD + kq + tig + 4];
            }
#pragma unroll
            for (int mi = 0; mi < 4; ++mi)
#pragma unroll
                for (int ni = 0; ni < 4; ++ni)
                    mma_tf32(acc[mi][ni][0], acc[mi][ni][1], acc[mi][ni][2], acc[mi][ni][3],
                             af[mi][0], af[mi][1], af[mi][2], af[mi][3],
                             bf[ni][0], bf[ni][1]);
        }

        // store prefetched regs into the other stage
        if (c + 1 < nch) {
            uint32_t* dA = smem + ((c + 1) & 1) * 2 * TILE_FLOATS;
            uint32_t* dB = dA + TILE_FLOATS;
#pragma unroll
            for (int j = 0; j < 4; ++j) {
                int r = lr0 + 32 * j;
                *reinterpret_cast<uint4*>(&dA[r * SAPAD + lc4 * 4]) = pa[j];
                *reinterpret_cast<uint4*>(&dB[r * SAPAD + lc4 * 4]) = pb[j];
            }
            __syncthreads();
        }
    }

    // epilogue
#pragma unroll
    for (int mi = 0; mi < 4; ++mi) {
        int row = m0 + wm + mi * 16 + gID;
#pragma unroll
        for (int ni = 0; ni < 4; ++ni) {
            int col = n0 + wn + ni * 8 + tig * 2;
            *reinterpret_cast<float2*>(C + (size_t)row * N + col) =
                make_float2(acc[mi][ni][0], acc[mi][ni][1]);
            *reinterpret_cast<float2*>(C + (size_t)(row + 8) * N + col) =
                make_float2(acc[mi][ni][2], acc[mi][ni][3]);
        }
    }
}

// ---------------------------------------------------------------------------
// RoPE: in-place on g_Q (NH heads) and g_K (NKV heads).
// ---------------------------------------------------------------------------
__global__ void rope_kernel(const float* __restrict__ cosb,
                            const float* __restrict__ sinb)
{
    const int total = BATCH * SEQ * (NHEADS + NKVH) * (HDIM / 2);
    int idx = blockIdx.x * blockDim.x + threadIdx.x;
    if (idx >= total) return;
    int d    = idx & 63;
    int rest = idx >> 6;
    int slot = rest % (NHEADS + NKVH);
    int bs   = rest / (NHEADS + NKVH);
    int s    = bs % SEQ;

    float c0 = cosb[s * HDIM + d];
    float c1 = cosb[s * HDIM + d + 64];
    float s0 = sinb[s * HDIM + d];
    float s1 = sinb[s * HDIM + d + 64];

    float* p;
    if (slot < NHEADS) p = g_Q + (bs * NHEADS + slot) * HDIM;
    else               p = g_K + (bs * NKVH + (slot - NHEADS)) * HDIM;

    float x0 = p[d], x1 = p[d + 64];
    p[d]      = x0 * c0 - x1 * s0;
    p[d + 64] = x1 * c1 + x0 * s1;
}

// ---------------------------------------------------------------------------
// Sliding-window GQA flash attention (fp32).
// ---------------------------------------------------------------------------
__global__ __launch_bounds__(128) void attn_kernel()
{
    constexpr int KT = 32;
    __shared__ float Ks[KT * HDIM];
    __shared__ float Vs[KT * HDIM];

    const int t    = threadIdx.x;
    const int r    = t >> 1;
    const int half = t & 1;
    const int q0   = blockIdx.x * 64;
    const int h    = blockIdx.y;
    const int b    = blockIdx.z;
    const int kvh  = h / GQA;
    const int q_idx = q0 + r;
    const int bS = b * SEQ;

    const float scale = 0.08838834764831845f;

    float qreg[64];
    {
        const float4* qp = reinterpret_cast<const float4*>(
            g_Q + ((bS + q_idx) * NHEADS + h) * HDIM + half * 64);
#pragma unroll
        for (int i = 0; i < 16; ++i) {
            float4 v = qp[i];
            qreg[4 * i + 0] = v.x * scale;
            qreg[4 * i + 1] = v.y * scale;
            qreg[4 * i + 2] = v.z * scale;
            qreg[4 * i + 3] = v.w * scale;
        }
    }

    float acc[64];
#pragma unroll
    for (int i = 0; i < 64; ++i) acc[i] = 0.f;
    float m_run = -1e30f, l_run = 0.f;

    const unsigned pmask = 3u << ((t & 31) & ~1);

    const float4* K4 = reinterpret_cast<const float4*>(g_K);
    const float4* V4 = reinterpret_cast<const float4*>(g_V);

    int jstart = q0 - (WIN - 1);
    if (jstart < 0) jstart = 0;
    jstart &= ~(KT - 1);

    for (int j0 = jstart; j0 < q0 + 64; j0 += KT) {
        __syncthreads();
#pragma unroll
        for (int i = t; i < KT * 32; i += 128) {
            int j  = i >> 5;
            int d4 = i & 31;
            int gi = ((bS + j0 + j) * NKVH + kvh) * 32 + d4;
            reinterpret_cast<float4*>(Ks)[i] = K4[gi];
            reinterpret_cast<float4*>(Vs)[i] = V4[gi];
        }
        __syncthreads();

        bool active = (j0 <= q_idx) && (q_idx - (j0 + KT - 1) < WIN);
        if (active) {
            float sreg[KT];
            float tmax = -1e30f;
#pragma unroll
            for (int j = 0; j < KT; ++j) {
                const float4* kp = reinterpret_cast<const float4*>(Ks + j * HDIM + half * 64);
                float p = 0.f;
#pragma unroll
                for (int dd = 0; dd < 16; ++dd) {
                    float4 kv = kp[dd];
                    p += qreg[4 * dd + 0] * kv.x + qreg[4 * dd + 1] * kv.y
                       + qreg[4 * dd + 2] * kv.z + qreg[4 * dd + 3] * kv.w;
                }
                p += __shfl_xor_sync(pmask, p, 1);
                int dist = q_idx - (j0 + j);
                sreg[j] = (dist >= 0 && dist < WIN) ? p : -1e30f;
                tmax = fmaxf(tmax, sreg[j]);
            }
            float mnew = fmaxf(m_run, tmax);
            float corr = __expf(m_run - mnew);
            l_run *= corr;
#pragma unroll
            for (int dd = 0; dd < 64; ++dd) acc[dd] *= corr;
#pragma unroll
            for (int j = 0; j < KT; ++j) {
                float p = __expf(sreg[j] - mnew);
                l_run += p;
                const float4* vp = reinterpret_cast<const float4*>(Vs + j * HDIM + half * 64);
#pragma unroll
                for (int dd = 0; dd < 16; ++dd) {
                    float4 vv = vp[dd];
                    acc[4 * dd + 0] += p * vv.x;
                    acc[4 * dd + 1] += p * vv.y;
                    acc[4 * dd + 2] += p * vv.z;
                    acc[4 * dd + 3] += p * vv.w;
                }
            }
            m_run = mnew;
        }
    }

    float inv = 1.f / l_run;
    float4* op = reinterpret_cast<float4*>(
        g_AO + ((bS + q_idx) * NHEADS + h) * HDIM + half * 64);
#pragma unroll
    for (int i = 0; i < 16; ++i) {
        op[i] = make_float4(acc[4 * i + 0] * inv, acc[4 * i + 1] * inv,
                            acc[4 * i + 2] * inv, acc[4 * i + 3] * inv);
    }
}

// ---------------------------------------------------------------------------
// Launch
// ---------------------------------------------------------------------------
extern "C" void kernel_launch(void* const* d_in, const int* in_sizes, int n_in,
                              void* d_out, int out_size)
{
    const float* x    = (const float*)d_in[0];
    const float* cosb = (const float*)d_in[1];
    const float* sinb = (const float*)d_in[2];
    const float* Wq   = (const float*)d_in[3];
    const float* Wk   = (const float*)d_in[4];
    const float* Wv   = (const float*)d_in[5];
    const float* Wo   = (const float*)d_in[6];
    float* out = (float*)d_out;

    float *Q, *K, *V, *AO;
    cudaGetSymbolAddress((void**)&Q,  g_Q);
    cudaGetSymbolAddress((void**)&K,  g_K);
    cudaGetSymbolAddress((void**)&V,  g_V);
    cudaGetSymbolAddress((void**)&AO, g_AO);

    static bool attr_done = false;
    if (!attr_done) {
        cudaFuncSetAttribute(gemm_mma, cudaFuncAttributeMaxDynamicSharedMemorySize, SMEM_GEMM);
        attr_done = true;
    }

    const int M = BATCH * SEQ;   // 4096

    // QKV projections (tf32 mma.sync)
    gemm_mma<<<dim3(EMB / 128, M / 128), 256, SMEM_GEMM>>>(x, Wq, Q, M, NHEADS * HDIM, EMB);
    gemm_mma<<<dim3((NKVH * HDIM) / 128, M / 128), 256, SMEM_GEMM>>>(x, Wk, K, M, NKVH * HDIM, EMB);
    gemm_mma<<<dim3((NKVH * HDIM) / 128, M / 128), 256, SMEM_GEMM>>>(x, Wv, V, M, NKVH * HDIM, EMB);

    // RoPE
    {
        int total = BATCH * SEQ * (NHEADS + NKVH) * (HDIM / 2);
        rope_kernel<<<(total + 255) / 256, 256>>>(cosb, sinb);
    }

    // Attention
    attn_kernel<<<dim3(SEQ / 64, NHEADS, BATCH), 128>>>();

    // Output projection
    gemm_mma<<<dim3(EMB / 128, M / 128), 256, SMEM_GEMM>>>(AO, Wo, out, M, EMB, EMB);
}

// round 4
// speedup vs baseline: 3.5566x; 2.2437x over previous
#include <cuda_runtime.h>
#include <cstdint>
#include <math.h>

// Problem constants
constexpr int BATCH  = 2;
constexpr int SEQ    = 2048;
constexpr int EMB    = 2048;
constexpr int NHEADS = 16;
constexpr int NKVH   = 4;
constexpr int HDIM   = 128;
constexpr int WIN    = 1024;
constexpr int GQA    = NHEADS / NKVH;

// Scratch
__device__ __align__(16) float g_Q [BATCH * SEQ * NHEADS * HDIM];
__device__ __align__(16) float g_K [BATCH * SEQ * NKVH   * HDIM];
__device__ __align__(16) float g_V [BATCH * SEQ * NKVH   * HDIM];
__device__ __align__(16) float g_AO[BATCH * SEQ * EMB];

__device__ __forceinline__ uint32_t f2tf32(float x) {
    uint32_t r;
    asm("cvt.rna.tf32.f32 %0, %1;" : "=r"(r) : "f"(x));
    return r;
}

__device__ __forceinline__ void mma_tf32(
    float& d0, float& d1, float& d2, float& d3,
    uint32_t a0, uint32_t a1, uint32_t a2, uint32_t a3,
    uint32_t b0, uint32_t b1)
{
    asm volatile(
        "mma.sync.aligned.m16n8k8.row.col.f32.tf32.tf32.f32 "
        "{%0,%1,%2,%3}, {%4,%5,%6,%7}, {%8,%9}, {%0,%1,%2,%3};"
        : "+f"(d0), "+f"(d1), "+f"(d2), "+f"(d3)
        : "r"(a0), "r"(a1), "r"(a2), "r"(a3), "r"(b0), "r"(b1));
}

// ===========================================================================
// TF32 mma.sync GEMM (NT): unchanged from R3 (passing, 5e-4).
// ===========================================================================
constexpr int BM = 128, BN = 128, BKC = 32;
constexpr int SAPAD = 36;
constexpr int TILE_FLOATS = BM * SAPAD;
constexpr int SMEM_GEMM = 2 * 2 * TILE_FLOATS * 4;

__global__ __launch_bounds__(256) void gemm_mma(
    const float* __restrict__ A, const float* __restrict__ B,
    float* __restrict__ C, int M, int N, int K)
{
    extern __shared__ uint32_t smem[];

    const int tid  = threadIdx.x;
    const int lane = tid & 31;
    const int wid  = tid >> 5;
    const int m0 = blockIdx.y * BM;
    const int n0 = blockIdx.x * BN;

    const int wm  = (wid >> 2) * 64;
    const int wn  = (wid & 3) * 32;
    const int gID = lane >> 2;
    const int tig = lane & 3;

    const int lr0 = tid >> 3;
    const int lc4 = tid & 7;

    const float* Abase = A + (size_t)(m0 + lr0) * K + lc4 * 4;
    const float* Bbase = B + (size_t)(n0 + lr0) * K + lc4 * 4;

    float acc[4][4][4];
#pragma unroll
    for (int mi = 0; mi < 4; ++mi)
#pragma unroll
        for (int ni = 0; ni < 4; ++ni)
#pragma unroll
            for (int q = 0; q < 4; ++q) acc[mi][ni][q] = 0.f;

    uint4 pa[4], pb[4];
    const int nch = K / BKC;

#pragma unroll
    for (int j = 0; j < 4; ++j) {
        float4 av = *reinterpret_cast<const float4*>(Abase + (size_t)(32 * j) * K);
        float4 bv = *reinterpret_cast<const float4*>(Bbase + (size_t)(32 * j) * K);
        pa[j] = make_uint4(f2tf32(av.x), f2tf32(av.y), f2tf32(av.z), f2tf32(av.w));
        pb[j] = make_uint4(f2tf32(bv.x), f2tf32(bv.y), f2tf32(bv.z), f2tf32(bv.w));
    }
#pragma unroll
    for (int j = 0; j < 4; ++j) {
        int r = lr0 + 32 * j;
        *reinterpret_cast<uint4*>(&smem[r * SAPAD + lc4 * 4]) = pa[j];
        *reinterpret_cast<uint4*>(&smem[TILE_FLOATS + r * SAPAD + lc4 * 4]) = pb[j];
    }
    __syncthreads();

    for (int c = 0; c < nch; ++c) {
        if (c + 1 < nch) {
            const int kb = (c + 1) * BKC;
#pragma unroll
            for (int j = 0; j < 4; ++j) {
                float4 av = *reinterpret_cast<const float4*>(Abase + (size_t)(32 * j) * K + kb);
                float4 bv = *reinterpret_cast<const float4*>(Bbase + (size_t)(32 * j) * K + kb);
                pa[j] = make_uint4(f2tf32(av.x), f2tf32(av.y), f2tf32(av.z), f2tf32(av.w));
                pb[j] = make_uint4(f2tf32(bv.x), f2tf32(bv.y), f2tf32(bv.z), f2tf32(bv.w));
            }
        }

        const uint32_t* sA = smem + (c & 1) * 2 * TILE_FLOATS;
        const uint32_t* sB = sA + TILE_FLOATS;
#pragma unroll
        for (int ks = 0; ks < 4; ++ks) {
            const int kq = ks * 8;
            uint32_t af[4][4], bf[4][2];
#pragma unroll
            for (int mi = 0; mi < 4; ++mi) {
                int row = wm + mi * 16 + gID;
                af[mi][0] = sA[row * SAPAD + kq + tig];
                af[mi][1] = sA[(row + 8) * SAPAD + kq + tig];
                af[mi][2] = sA[row * SAPAD + kq + tig + 4];
                af[mi][3] = sA[(row + 8) * SAPAD + kq + tig + 4];
            }
#pragma unroll
            for (int ni = 0; ni < 4; ++ni) {
                int col = wn + ni * 8 + gID;
                bf[ni][0] = sB[col * SAPAD + kq + tig];
                bf[ni][1] = sB[col * SAPAD + kq + tig + 4];
            }
#pragma unroll
            for (int mi = 0; mi < 4; ++mi)
#pragma unroll
                for (int ni = 0; ni < 4; ++ni)
                    mma_tf32(acc[mi][ni][0], acc[mi][ni][1], acc[mi][ni][2], acc[mi][ni][3],
                             af[mi][0], af[mi][1], af[mi][2], af[mi][3],
                             bf[ni][0], bf[ni][1]);
        }

        if (c + 1 < nch) {
            uint32_t* dA = smem + ((c + 1) & 1) * 2 * TILE_FLOATS;
            uint32_t* dB = dA + TILE_FLOATS;
#pragma unroll
            for (int j = 0; j < 4; ++j) {
                int r = lr0 + 32 * j;
                *reinterpret_cast<uint4*>(&dA[r * SAPAD + lc4 * 4]) = pa[j];
                *reinterpret_cast<uint4*>(&dB[r * SAPAD + lc4 * 4]) = pb[j];
            }
            __syncthreads();
        }
    }

#pragma unroll
    for (int mi = 0; mi < 4; ++mi) {
        int row = m0 + wm + mi * 16 + gID;
#pragma unroll
        for (int ni = 0; ni < 4; ++ni) {
            int col = n0 + wn + ni * 8 + tig * 2;
            *reinterpret_cast<float2*>(C + (size_t)row * N + col) =
                make_float2(acc[mi][ni][0], acc[mi][ni][1]);
            *reinterpret_cast<float2*>(C + (size_t)(row + 8) * N + col) =
                make_float2(acc[mi][ni][2], acc[mi][ni][3]);
        }
    }
}

// ---------------------------------------------------------------------------
// RoPE (unchanged)
// ---------------------------------------------------------------------------
__global__ void rope_kernel(const float* __restrict__ cosb,
                            const float* __restrict__ sinb)
{
    const int total = BATCH * SEQ * (NHEADS + NKVH) * (HDIM / 2);
    int idx = blockIdx.x * blockDim.x + threadIdx.x;
    if (idx >= total) return;
    int d    = idx & 63;
    int rest = idx >> 6;
    int slot = rest % (NHEADS + NKVH);
    int bs   = rest / (NHEADS + NKVH);
    int s    = bs % SEQ;

    float c0 = cosb[s * HDIM + d];
    float c1 = cosb[s * HDIM + d + 64];
    float s0 = sinb[s * HDIM + d];
    float s1 = sinb[s * HDIM + d + 64];

    float* p;
    if (slot < NHEADS) p = g_Q + (bs * NHEADS + slot) * HDIM;
    else               p = g_K + (bs * NKVH + (slot - NHEADS)) * HDIM;

    float x0 = p[d], x1 = p[d + 64];
    p[d]      = x0 * c0 - x1 * s0;
    p[d + 64] = x1 * c1 + x0 * s1;
}

// ===========================================================================
// TF32 MMA flash attention, sliding window, GQA.
// Block: 64 queries x (b,h). 4 warps x 16 rows. KT=32 key tiles.
// ===========================================================================
constexpr int KSTRIDE = 132;   // Ks row stride (banks: g*4+t, conflict-free)
constexpr int VSTRIDE = 136;   // Vs row stride (banks: t*8+g, conflict-free)
constexpr int QSTRIDE = 132;
constexpr int PSTRIDE = 36;

constexpr int KS_OFF = 0;                       // 32*132 = 4224
constexpr int VS_OFF = KS_OFF + 32 * KSTRIDE;   // 4224
constexpr int QP_OFF = VS_OFF + 32 * VSTRIDE;   // 8576; Q staging 64*132=8448, reused for P
constexpr int SMEM_ATTN = (QP_OFF + 64 * QSTRIDE) * 4;   // 68096 bytes

__global__ __launch_bounds__(128) void attn_mma_kernel()
{
    extern __shared__ uint32_t sm[];

    const int tid  = threadIdx.x;
    const int lane = tid & 31;
    const int wq   = tid >> 5;          // warp id: rows [wq*16, wq*16+16)
    const int g    = lane >> 2;         // group 0..7
    const int t    = lane & 3;          // 0..3

    const int q0  = blockIdx.x * 64;
    const int h   = blockIdx.y;
    const int b   = blockIdx.z;
    const int kvh = h / GQA;
    const int bS  = b * SEQ;
    const int qw  = q0 + wq * 16;       // this warp's first row

    const float scale = 0.08838834764831845f;

    // ---- stage Q (scaled, tf32) into smem, then extract A-fragments ----
    {
        const float* Qg = g_Q + ((size_t)(bS + q0) * NHEADS + h) * HDIM;
        // 64 rows x 32 float4 = 2048 float4; 128 threads -> 16 each
#pragma unroll
        for (int i = tid; i < 2048; i += 128) {
            int r  = i >> 5;
            int c4 = i & 31;
            float4 v = *reinterpret_cast<const float4*>(Qg + (size_t)r * NHEADS * HDIM + c4 * 4);
            uint32_t* dst = &sm[QP_OFF + r * QSTRIDE + c4 * 4];
            dst[0] = f2tf32(v.x * scale);
            dst[1] = f2tf32(v.y * scale);
            dst[2] = f2tf32(v.z * scale);
            dst[3] = f2tf32(v.w * scale);
        }
    }
    __syncthreads();

    uint32_t qf[16][4];
#pragma unroll
    for (int kk = 0; kk < 16; ++kk) {
        int r0 = (wq * 16 + g) * QSTRIDE + kk * 8 + t;
        qf[kk][0] = sm[QP_OFF + r0];
        qf[kk][1] = sm[QP_OFF + r0 + 8 * QSTRIDE];
        qf[kk][2] = sm[QP_OFF + r0 + 4];
        qf[kk][3] = sm[QP_OFF + r0 + 8 * QSTRIDE + 4];
    }
    __syncthreads();   // Q region now reusable as P scratch

    uint32_t* Pw = &sm[QP_OFF + wq * 1024];   // per-warp P patch [16][36]

    // ---- softmax state (2 row-halves per thread) ----
    float m0r = -1e30f, m1r = -1e30f, l0 = 0.f, l1 = 0.f;
    float oacc[16][4];
#pragma unroll
    for (int ni = 0; ni < 16; ++ni)
#pragma unroll
        for (int qd = 0; qd < 4; ++qd) oacc[ni][qd] = 0.f;

    int jstart = q0 - (WIN - 1);
    if (jstart < 0) jstart = 0;
    jstart &= ~31;

    for (int j0 = jstart; j0 < q0 + 64; j0 += 32) {
        // ---- stage K/V tile (tf32) ----
        __syncthreads();
        {
            const float* Kg = g_K + ((size_t)(bS + j0) * NKVH + kvh) * HDIM;
            const float* Vg = g_V + ((size_t)(bS + j0) * NKVH + kvh) * HDIM;
#pragma unroll
            for (int i = tid; i < 1024; i += 128) {
                int r  = i >> 5;
                int c4 = i & 31;
                size_t goff = (size_t)r * NKVH * HDIM + c4 * 4;
                float4 kv = *reinterpret_cast<const float4*>(Kg + goff);
                float4 vv = *reinterpret_cast<const float4*>(Vg + goff);
                uint32_t* kd = &sm[KS_OFF + r * KSTRIDE + c4 * 4];
                kd[0] = f2tf32(kv.x); kd[1] = f2tf32(kv.y);
                kd[2] = f2tf32(kv.z); kd[3] = f2tf32(kv.w);
                uint32_t* vd = &sm[VS_OFF + r * VSTRIDE + c4 * 4];
                vd[0] = f2tf32(vv.x); vd[1] = f2tf32(vv.y);
                vd[2] = f2tf32(vv.z); vd[3] = f2tf32(vv.w);
            }
        }
        __syncthreads();

        // per-warp window skip
        if (j0 > qw + 15) continue;                 // all-future
        if (qw - (j0 + 31) >= WIN) continue;        // all-expired

        // ---- QK^T: scores[16 q][32 keys] ----
        float sc[4][4];
#pragma unroll
        for (int ni = 0; ni < 4; ++ni)
#pragma unroll
            for (int qd = 0; qd < 4; ++qd) sc[ni][qd] = 0.f;

#pragma unroll
        for (int kk = 0; kk < 16; ++kk) {
#pragma unroll
            for (int ni = 0; ni < 4; ++ni) {
                uint32_t b0 = sm[KS_OFF + (ni * 8 + g) * KSTRIDE + kk * 8 + t];
                uint32_t b1 = sm[KS_OFF + (ni * 8 + g) * KSTRIDE + kk * 8 + t + 4];
                mma_tf32(sc[ni][0], sc[ni][1], sc[ni][2], sc[ni][3],
                         qf[kk][0], qf[kk][1], qf[kk][2], qf[kk][3], b0, b1);
            }
        }

        // ---- mask + row max ----
        const int r0 = qw + g;       // rows r0 (c0,c1) and r0+8 (c2,c3)
        float tmax0 = -1e30f, tmax1 = -1e30f;
#pragma unroll
        for (int ni = 0; ni < 4; ++ni) {
            int col0 = j0 + ni * 8 + 2 * t;
#pragma unroll
            for (int cc = 0; cc < 2; ++cc) {
                int col = col0 + cc;
                int d0 = r0 - col;
                int d1 = r0 + 8 - col;
                if (!(d0 >= 0 && d0 < WIN)) sc[ni][cc]     = -1e30f;
                if (!(d1 >= 0 && d1 < WIN)) sc[ni][cc + 2] = -1e30f;
                tmax0 = fmaxf(tmax0, sc[ni][cc]);
                tmax1 = fmaxf(tmax1, sc[ni][cc + 2]);
            }
        }
        tmax0 = fmaxf(tmax0, __shfl_xor_sync(0xffffffffu, tmax0, 1));
        tmax0 = fmaxf(tmax0, __shfl_xor_sync(0xffffffffu, tmax0, 2));
        tmax1 = fmaxf(tmax1, __shfl_xor_sync(0xffffffffu, tmax1, 1));
        tmax1 = fmaxf(tmax1, __shfl_xor_sync(0xffffffffu, tmax1, 2));

        float mn0 = fmaxf(m0r, tmax0);
        float mn1 = fmaxf(m1r, tmax1);
        float cor0 = __expf(m0r - mn0);
        float cor1 = __expf(m1r - mn1);
        m0r = mn0; m1r = mn1;

        // ---- exponentiate, write P (tf32) to smem, accumulate l ----
        float ps0 = 0.f, ps1 = 0.f;
#pragma unroll
        for (int ni = 0; ni < 4; ++ni) {
#pragma unroll
            for (int cc = 0; cc < 2; ++cc) {
                float p0 = (sc[ni][cc]     > -1e29f) ? __expf(sc[ni][cc]     - mn0) : 0.f;
                float p1 = (sc[ni][cc + 2] > -1e29f) ? __expf(sc[ni][cc + 2] - mn1) : 0.f;
                ps0 += p0; ps1 += p1;
                int colL = ni * 8 + 2 * t + cc;
                Pw[g * PSTRIDE + colL]       = f2tf32(p0);
                Pw[(g + 8) * PSTRIDE + colL] = f2tf32(p1);
            }
        }
        ps0 += __shfl_xor_sync(0xffffffffu, ps0, 1);
        ps0 += __shfl_xor_sync(0xffffffffu, ps0, 2);
        ps1 += __shfl_xor_sync(0xffffffffu, ps1, 1);
        ps1 += __shfl_xor_sync(0xffffffffu, ps1, 2);
        l0 = l0 * cor0 + ps0;
        l1 = l1 * cor1 + ps1;

        // rescale output accumulators
#pragma unroll
        for (int ni = 0; ni < 16; ++ni) {
            oacc[ni][0] *= cor0; oacc[ni][1] *= cor0;
            oacc[ni][2] *= cor1; oacc[ni][3] *= cor1;
        }

        __syncwarp();

        // ---- PV: out += P[16x32] * V[32x128] ----
#pragma unroll
        for (int kc = 0; kc < 4; ++kc) {
            uint32_t a0 = Pw[g * PSTRIDE + kc * 8 + t];
            uint32_t a1 = Pw[(g + 8) * PSTRIDE + kc * 8 + t];
            uint32_t a2 = Pw[g * PSTRIDE + kc * 8 + t + 4];
            uint32_t a3 = Pw[(g + 8) * PSTRIDE + kc * 8 + t + 4];
#pragma unroll
            for (int ni = 0; ni < 16; ++ni) {
                uint32_t b0 = sm[VS_OFF + (kc * 8 + t) * VSTRIDE + ni * 8 + g];
                uint32_t b1 = sm[VS_OFF + (kc * 8 + t + 4) * VSTRIDE + ni * 8 + g];
                mma_tf32(oacc[ni][0], oacc[ni][1], oacc[ni][2], oacc[ni][3],
                         a0, a1, a2, a3, b0, b1);
            }
        }
        __syncwarp();   // P patch reuse next tile
    }

    // ---- normalize + store ----
    float inv0 = 1.f / l0;
    float inv1 = 1.f / l1;
    float* Og = g_AO + ((size_t)(bS + qw + g) * NHEADS + h) * HDIM;
    float* Og8 = Og + (size_t)8 * NHEADS * HDIM;
#pragma unroll
    for (int ni = 0; ni < 16; ++ni) {
        int col = ni * 8 + 2 * t;
        *reinterpret_cast<float2*>(Og + col)  = make_float2(oacc[ni][0] * inv0, oacc[ni][1] * inv0);
        *reinterpret_cast<float2*>(Og8 + col) = make_float2(oacc[ni][2] * inv1, oacc[ni][3] * inv1);
    }
}

// ---------------------------------------------------------------------------
// Launch
// ---------------------------------------------------------------------------
extern "C" void kernel_launch(void* const* d_in, const int* in_sizes, int n_in,
                              void* d_out, int out_size)
{
    const float* x    = (const float*)d_in[0];
    const float* cosb = (const float*)d_in[1];
    const float* sinb = (const float*)d_in[2];
    const float* Wq   = (const float*)d_in[3];
    const float* Wk   = (const float*)d_in[4];
    const float* Wv   = (const float*)d_in[5];
    const float* Wo   = (const float*)d_in[6];
    float* out = (float*)d_out;

    float *Q, *K, *V, *AO;
    cudaGetSymbolAddress((void**)&Q,  g_Q);
    cudaGetSymbolAddress((void**)&K,  g_K);
    cudaGetSymbolAddress((void**)&V,  g_V);
    cudaGetSymbolAddress((void**)&AO, g_AO);

    static bool attr_done = false;
    if (!attr_done) {
        cudaFuncSetAttribute(gemm_mma, cudaFuncAttributeMaxDynamicSharedMemorySize, SMEM_GEMM);
        cudaFuncSetAttribute(attn_mma_kernel, cudaFuncAttributeMaxDynamicSharedMemorySize, SMEM_ATTN);
        attr_done = true;
    }

    const int M = BATCH * SEQ;

    gemm_mma<<<dim3(EMB / 128, M / 128), 256, SMEM_GEMM>>>(x, Wq, Q, M, NHEADS * HDIM, EMB);
    gemm_mma<<<dim3((NKVH * HDIM) / 128, M / 128), 256, SMEM_GEMM>>>(x, Wk, K, M, NKVH * HDIM, EMB);
    gemm_mma<<<dim3((NKVH * HDIM) / 128, M / 128), 256, SMEM_GEMM>>>(x, Wv, V, M, NKVH * HDIM, EMB);

    {
        int total = BATCH * SEQ * (NHEADS + NKVH) * (HDIM / 2);
        rope_kernel<<<(total + 255) / 256, 256>>>(cosb, sinb);
    }

    attn_mma_kernel<<<dim3(SEQ / 64, NHEADS, BATCH), 128, SMEM_ATTN>>>();

    gemm_mma<<<dim3(EMB / 128, M / 128), 256, SMEM_GEMM>>>(AO, Wo, out, M, EMB, EMB);
}

// round 5
// speedup vs baseline: 3.5846x; 1.0079x over previous
#include <cuda_runtime.h>
#include <cstdint>
#include <math.h>

// Problem constants
constexpr int BATCH  = 2;
constexpr int SEQ    = 2048;
constexpr int EMB    = 2048;
constexpr int NHEADS = 16;
constexpr int NKVH   = 4;
constexpr int HDIM   = 128;
constexpr int WIN    = 1024;
constexpr int GQA    = NHEADS / NKVH;

// Scratch
__device__ __align__(16) float g_Q [BATCH * SEQ * NHEADS * HDIM];
__device__ __align__(16) float g_K [BATCH * SEQ * NKVH   * HDIM];
__device__ __align__(16) float g_V [BATCH * SEQ * NKVH   * HDIM];
__device__ __align__(16) float g_AO[BATCH * SEQ * EMB];

__device__ __forceinline__ uint32_t f2tf32(float x) {
    uint32_t r;
    asm("cvt.rna.tf32.f32 %0, %1;" : "=r"(r) : "f"(x));
    return r;
}
__device__ __forceinline__ float ex2(float x) {
    float r;
    asm("ex2.approx.f32 %0, %1;" : "=f"(r) : "f"(x));
    return r;
}

__device__ __forceinline__ void mma_tf32(
    float& d0, float& d1, float& d2, float& d3,
    uint32_t a0, uint32_t a1, uint32_t a2, uint32_t a3,
    uint32_t b0, uint32_t b1)
{
    asm volatile(
        "mma.sync.aligned.m16n8k8.row.col.f32.tf32.tf32.f32 "
        "{%0,%1,%2,%3}, {%4,%5,%6,%7}, {%8,%9}, {%0,%1,%2,%3};"
        : "+f"(d0), "+f"(d1), "+f"(d2), "+f"(d3)
        : "r"(a0), "r"(a1), "r"(a2), "r"(a3), "r"(b0), "r"(b1));
}

// ===========================================================================
// TF32 mma.sync GEMM body (NT): C[M,N] = A[M,K] * B[N,K]^T, row-major.
// 128x128x32 CTA tile, 256 threads, 8 warps (2x4), double-buffered smem.
// ===========================================================================
constexpr int BM = 128, BN = 128, BKC = 32;
constexpr int SAPAD = 36;
constexpr int TILE_FLOATS = BM * SAPAD;
constexpr int SMEM_GEMM = 2 * 2 * TILE_FLOATS * 4;

__device__ __forceinline__ void gemm_body(
    const float* __restrict__ A, const float* __restrict__ B,
    float* __restrict__ C, int M, int N, int K,
    int bx, int by, uint32_t* smem)
{
    const int tid  = threadIdx.x;
    const int lane = tid & 31;
    const int wid  = tid >> 5;
    const int m0 = by * BM;
    const int n0 = bx * BN;

    const int wm  = (wid >> 2) * 64;
    const int wn  = (wid & 3) * 32;
    const int gID = lane >> 2;
    const int tig = lane & 3;

    const int lr0 = tid >> 3;
    const int lc4 = tid & 7;

    const float* Abase = A + (size_t)(m0 + lr0) * K + lc4 * 4;
    const float* Bbase = B + (size_t)(n0 + lr0) * K + lc4 * 4;

    float acc[4][4][4];
#pragma unroll
    for (int mi = 0; mi < 4; ++mi)
#pragma unroll
        for (int ni = 0; ni < 4; ++ni)
#pragma unroll
            for (int q = 0; q < 4; ++q) acc[mi][ni][q] = 0.f;

    uint4 pa[4], pb[4];
    const int nch = K / BKC;

#pragma unroll
    for (int j = 0; j < 4; ++j) {
        float4 av = *reinterpret_cast<const float4*>(Abase + (size_t)(32 * j) * K);
        float4 bv = *reinterpret_cast<const float4*>(Bbase + (size_t)(32 * j) * K);
        pa[j] = make_uint4(f2tf32(av.x), f2tf32(av.y), f2tf32(av.z), f2tf32(av.w));
        pb[j] = make_uint4(f2tf32(bv.x), f2tf32(bv.y), f2tf32(bv.z), f2tf32(bv.w));
    }
#pragma unroll
    for (int j = 0; j < 4; ++j) {
        int r = lr0 + 32 * j;
        *reinterpret_cast<uint4*>(&smem[r * SAPAD + lc4 * 4]) = pa[j];
        *reinterpret_cast<uint4*>(&smem[TILE_FLOATS + r * SAPAD + lc4 * 4]) = pb[j];
    }
    __syncthreads();

    for (int c = 0; c < nch; ++c) {
        if (c + 1 < nch) {
            const int kb = (c + 1) * BKC;
#pragma unroll
            for (int j = 0; j < 4; ++j) {
                float4 av = *reinterpret_cast<const float4*>(Abase + (size_t)(32 * j) * K + kb);
                float4 bv = *reinterpret_cast<const float4*>(Bbase + (size_t)(32 * j) * K + kb);
                pa[j] = make_uint4(f2tf32(av.x), f2tf32(av.y), f2tf32(av.z), f2tf32(av.w));
                pb[j] = make_uint4(f2tf32(bv.x), f2tf32(bv.y), f2tf32(bv.z), f2tf32(bv.w));
            }
        }

        const uint32_t* sA = smem + (c & 1) * 2 * TILE_FLOATS;
        const uint32_t* sB = sA + TILE_FLOATS;
#pragma unroll
        for (int ks = 0; ks < 4; ++ks) {
            const int kq = ks * 8;
            uint32_t af[4][4], bf[4][2];
#pragma unroll
            for (int mi = 0; mi < 4; ++mi) {
                int row = wm + mi * 16 + gID;
                af[mi][0] = sA[row * SAPAD + kq + tig];
                af[mi][1] = sA[(row + 8) * SAPAD + kq + tig];
                af[mi][2] = sA[row * SAPAD + kq + tig + 4];
                af[mi][3] = sA[(row + 8) * SAPAD + kq + tig + 4];
            }
#pragma unroll
            for (int ni = 0; ni < 4; ++ni) {
                int col = wn + ni * 8 + gID;
                bf[ni][0] = sB[col * SAPAD + kq + tig];
                bf[ni][1] = sB[col * SAPAD + kq + tig + 4];
            }
#pragma unroll
            for (int mi = 0; mi < 4; ++mi)
#pragma unroll
                for (int ni = 0; ni < 4; ++ni)
                    mma_tf32(acc[mi][ni][0], acc[mi][ni][1], acc[mi][ni][2], acc[mi][ni][3],
                             af[mi][0], af[mi][1], af[mi][2], af[mi][3],
                             bf[ni][0], bf[ni][1]);
        }

        if (c + 1 < nch) {
            uint32_t* dA = smem + ((c + 1) & 1) * 2 * TILE_FLOATS;
            uint32_t* dB = dA + TILE_FLOATS;
#pragma unroll
            for (int j = 0; j < 4; ++j) {
                int r = lr0 + 32 * j;
                *reinterpret_cast<uint4*>(&dA[r * SAPAD + lc4 * 4]) = pa[j];
                *reinterpret_cast<uint4*>(&dB[r * SAPAD + lc4 * 4]) = pb[j];
            }
            __syncthreads();
        }
    }

#pragma unroll
    for (int mi = 0; mi < 4; ++mi) {
        int row = m0 + wm + mi * 16 + gID;
#pragma unroll
        for (int ni = 0; ni < 4; ++ni) {
            int col = n0 + wn + ni * 8 + tig * 2;
            *reinterpret_cast<float2*>(C + (size_t)row * N + col) =
                make_float2(acc[mi][ni][0], acc[mi][ni][1]);
            *reinterpret_cast<float2*>(C + (size_t)(row + 8) * N + col) =
                make_float2(acc[mi][ni][2], acc[mi][ni][3]);
        }
    }
}

__global__ __launch_bounds__(256) void gemm_mma(
    const float* __restrict__ A, const float* __restrict__ B,
    float* __restrict__ C, int M, int N, int K)
{
    extern __shared__ uint32_t smem[];
    gemm_body(A, B, C, M, N, K, blockIdx.x, blockIdx.y, smem);
}

// Fused K & V projection: blockIdx.z selects weight/output.
__global__ __launch_bounds__(256) void gemm_kv(
    const float* __restrict__ A,
    const float* __restrict__ Wk, const float* __restrict__ Wv,
    float* __restrict__ Kout, float* __restrict__ Vout,
    int M, int N, int K)
{
    extern __shared__ uint32_t smem[];
    const float* B = (blockIdx.z == 0) ? Wk : Wv;
    float* C       = (blockIdx.z == 0) ? Kout : Vout;
    gemm_body(A, B, C, M, N, K, blockIdx.x, blockIdx.y, smem);
}

// ---------------------------------------------------------------------------
// RoPE (unchanged)
// ---------------------------------------------------------------------------
__global__ void rope_kernel(const float* __restrict__ cosb,
                            const float* __restrict__ sinb)
{
    const int total = BATCH * SEQ * (NHEADS + NKVH) * (HDIM / 2);
    int idx = blockIdx.x * blockDim.x + threadIdx.x;
    if (idx >= total) return;
    int d    = idx & 63;
    int rest = idx >> 6;
    int slot = rest % (NHEADS + NKVH);
    int bs   = rest / (NHEADS + NKVH);
    int s    = bs % SEQ;

    float c0 = cosb[s * HDIM + d];
    float c1 = cosb[s * HDIM + d + 64];
    float s0 = sinb[s * HDIM + d];
    float s1 = sinb[s * HDIM + d + 64];

    float* p;
    if (slot < NHEADS) p = g_Q + (bs * NHEADS + slot) * HDIM;
    else               p = g_K + (bs * NKVH + (slot - NHEADS)) * HDIM;

    float x0 = p[d], x1 = p[d + 64];
    p[d]      = x0 * c0 - x1 * s0;
    p[d + 64] = x1 * c1 + x0 * s1;
}

// ===========================================================================
// TF32 MMA flash attention, sliding window, GQA.  exp2-domain softmax.
// Block: 64 queries x (b,h). 4 warps x 16 rows. KT=32 key tiles.
// ===========================================================================
constexpr int KSTRIDE = 132;
constexpr int VSTRIDE = 136;
constexpr int QSTRIDE = 132;
constexpr int PSTRIDE = 36;

constexpr int KS_OFF = 0;
constexpr int VS_OFF = KS_OFF + 32 * KSTRIDE;
constexpr int QP_OFF = VS_OFF + 32 * VSTRIDE;
constexpr int SMEM_ATTN = (QP_OFF + 64 * QSTRIDE) * 4;

__global__ __launch_bounds__(128) void attn_mma_kernel()
{
    extern __shared__ uint32_t sm[];

    const int tid  = threadIdx.x;
    const int lane = tid & 31;
    const int wq   = tid >> 5;
    const int g    = lane >> 2;
    const int t    = lane & 3;

    const int q0  = blockIdx.x * 64;
    const int h   = blockIdx.y;
    const int b   = blockIdx.z;
    const int kvh = h / GQA;
    const int bS  = b * SEQ;
    const int qw  = q0 + wq * 16;

    // scale * log2(e): scores land directly in log2 domain
    const float scale = 0.08838834764831845f * 1.4426950408889634f;

    // ---- stage Q (scaled, tf32, exp2-domain) ----
    {
        const float* Qg = g_Q + ((size_t)(bS + q0) * NHEADS + h) * HDIM;
#pragma unroll
        for (int i = tid; i < 2048; i += 128) {
            int r  = i >> 5;
            int c4 = i & 31;
            float4 v = *reinterpret_cast<const float4*>(Qg + (size_t)r * NHEADS * HDIM + c4 * 4);
            *reinterpret_cast<uint4*>(&sm[QP_OFF + r * QSTRIDE + c4 * 4]) =
                make_uint4(f2tf32(v.x * scale), f2tf32(v.y * scale),
                           f2tf32(v.z * scale), f2tf32(v.w * scale));
        }
    }
    __syncthreads();

    uint32_t qf[16][4];
#pragma unroll
    for (int kk = 0; kk < 16; ++kk) {
        int r0 = (wq * 16 + g) * QSTRIDE + kk * 8 + t;
        qf[kk][0] = sm[QP_OFF + r0];
        qf[kk][1] = sm[QP_OFF + r0 + 8 * QSTRIDE];
        qf[kk][2] = sm[QP_OFF + r0 + 4];
        qf[kk][3] = sm[QP_OFF + r0 + 8 * QSTRIDE + 4];
    }
    __syncthreads();

    uint32_t* Pw = &sm[QP_OFF + wq * 1024];

    float m0r = -1e30f, m1r = -1e30f, l0 = 0.f, l1 = 0.f;
    float oacc[16][4];
#pragma unroll
    for (int ni = 0; ni < 16; ++ni)
#pragma unroll
        for (int qd = 0; qd < 4; ++qd) oacc[ni][qd] = 0.f;

    int jstart = q0 - (WIN - 1);
    if (jstart < 0) jstart = 0;
    jstart &= ~31;

    for (int j0 = jstart; j0 < q0 + 64; j0 += 32) {
        __syncthreads();
        {
            const float* Kg = g_K + ((size_t)(bS + j0) * NKVH + kvh) * HDIM;
            const float* Vg = g_V + ((size_t)(bS + j0) * NKVH + kvh) * HDIM;
#pragma unroll
            for (int i = tid; i < 1024; i += 128) {
                int r  = i >> 5;
                int c4 = i & 31;
                size_t goff = (size_t)r * NKVH * HDIM + c4 * 4;
                float4 kv = *reinterpret_cast<const float4*>(Kg + goff);
                float4 vv = *reinterpret_cast<const float4*>(Vg + goff);
                *reinterpret_cast<uint4*>(&sm[KS_OFF + r * KSTRIDE + c4 * 4]) =
                    make_uint4(f2tf32(kv.x), f2tf32(kv.y), f2tf32(kv.z), f2tf32(kv.w));
                *reinterpret_cast<uint4*>(&sm[VS_OFF + r * VSTRIDE + c4 * 4]) =
                    make_uint4(f2tf32(vv.x), f2tf32(vv.y), f2tf32(vv.z), f2tf32(vv.w));
            }
        }
        __syncthreads();

        if (j0 > qw + 15) continue;
        if (qw - (j0 + 31) >= WIN) continue;

        float sc[4][4];
#pragma unroll
        for (int ni = 0; ni < 4; ++ni)
#pragma unroll
            for (int qd = 0; qd < 4; ++qd) sc[ni][qd] = 0.f;

#pragma unroll
        for (int kk = 0; kk < 16; ++kk) {
#pragma unroll
            for (int ni = 0; ni < 4; ++ni) {
                uint32_t b0 = sm[KS_OFF + (ni * 8 + g) * KSTRIDE + kk * 8 + t];
                uint32_t b1 = sm[KS_OFF + (ni * 8 + g) * KSTRIDE + kk * 8 + t + 4];
                mma_tf32(sc[ni][0], sc[ni][1], sc[ni][2], sc[ni][3],
                         qf[kk][0], qf[kk][1], qf[kk][2], qf[kk][3], b0, b1);
            }
        }

        const int r0 = qw + g;
        float tmax0 = -1e30f, tmax1 = -1e30f;
#pragma unroll
        for (int ni = 0; ni < 4; ++ni) {
            int col0 = j0 + ni * 8 + 2 * t;
#pragma unroll
            for (int cc = 0; cc < 2; ++cc) {
                int col = col0 + cc;
                int d0 = r0 - col;
                int d1 = r0 + 8 - col;
                if (!(d0 >= 0 && d0 < WIN)) sc[ni][cc]     = -1e30f;
                if (!(d1 >= 0 && d1 < WIN)) sc[ni][cc + 2] = -1e30f;
                tmax0 = fmaxf(tmax0, sc[ni][cc]);
                tmax1 = fmaxf(tmax1, sc[ni][cc + 2]);
            }
        }
        tmax0 = fmaxf(tmax0, __shfl_xor_sync(0xffffffffu, tmax0, 1));
        tmax0 = fmaxf(tmax0, __shfl_xor_sync(0xffffffffu, tmax0, 2));
        tmax1 = fmaxf(tmax1, __shfl_xor_sync(0xffffffffu, tmax1, 1));
        tmax1 = fmaxf(tmax1, __shfl_xor_sync(0xffffffffu, tmax1, 2));

        float mn0 = fmaxf(m0r, tmax0);
        float mn1 = fmaxf(m1r, tmax1);
        float cor0 = ex2(m0r - mn0);
        float cor1 = ex2(m1r - mn1);
        m0r = mn0; m1r = mn1;

        float ps0 = 0.f, ps1 = 0.f;
#pragma unroll
        for (int ni = 0; ni < 4; ++ni) {
#pragma unroll
            for (int cc = 0; cc < 2; ++cc) {
                float p0 = (sc[ni][cc]     > -1e29f) ? ex2(sc[ni][cc]     - mn0) : 0.f;
                float p1 = (sc[ni][cc + 2] > -1e29f) ? ex2(sc[ni][cc + 2] - mn1) : 0.f;
                ps0 += p0; ps1 += p1;
                int colL = ni * 8 + 2 * t + cc;
                Pw[g * PSTRIDE + colL]       = f2tf32(p0);
                Pw[(g + 8) * PSTRIDE + colL] = f2tf32(p1);
            }
        }
        ps0 += __shfl_xor_sync(0xffffffffu, ps0, 1);
        ps0 += __shfl_xor_sync(0xffffffffu, ps0, 2);
        ps1 += __shfl_xor_sync(0xffffffffu, ps1, 1);
        ps1 += __shfl_xor_sync(0xffffffffu, ps1, 2);
        l0 = l0 * cor0 + ps0;
        l1 = l1 * cor1 + ps1;

#pragma unroll
        for (int ni = 0; ni < 16; ++ni) {
            oacc[ni][0] *= cor0; oacc[ni][1] *= cor0;
            oacc[ni][2] *= cor1; oacc[ni][3] *= cor1;
        }

        __syncwarp();

#pragma unroll
        for (int kc = 0; kc < 4; ++kc) {
            uint32_t a0 = Pw[g * PSTRIDE + kc * 8 + t];
            uint32_t a1 = Pw[(g + 8) * PSTRIDE + kc * 8 + t];
            uint32_t a2 = Pw[g * PSTRIDE + kc * 8 + t + 4];
            uint32_t a3 = Pw[(g + 8) * PSTRIDE + kc * 8 + t + 4];
#pragma unroll
            for (int ni = 0; ni < 16; ++ni) {
                uint32_t b0 = sm[VS_OFF + (kc * 8 + t) * VSTRIDE + ni * 8 + g];
                uint32_t b1 = sm[VS_OFF + (kc * 8 + t + 4) * VSTRIDE + ni * 8 + g];
                mma_tf32(oacc[ni][0], oacc[ni][1], oacc[ni][2], oacc[ni][3],
                         a0, a1, a2, a3, b0, b1);
            }
        }
        __syncwarp();
    }

    float inv0 = 1.f / l0;
    float inv1 = 1.f / l1;
    float* Og = g_AO + ((size_t)(bS + qw + g) * NHEADS + h) * HDIM;
    float* Og8 = Og + (size_t)8 * NHEADS * HDIM;
#pragma unroll
    for (int ni = 0; ni < 16; ++ni) {
        int col = ni * 8 + 2 * t;
        *reinterpret_cast<float2*>(Og + col)  = make_float2(oacc[ni][0] * inv0, oacc[ni][1] * inv0);
        *reinterpret_cast<float2*>(Og8 + col) = make_float2(oacc[ni][2] * inv1, oacc[ni][3] * inv1);
    }
}

// ---------------------------------------------------------------------------
// Launch
// ---------------------------------------------------------------------------
extern "C" void kernel_launch(void* const* d_in, const int* in_sizes, int n_in,
                              void* d_out, int out_size)
{
    const float* x    = (const float*)d_in[0];
    const float* cosb = (const float*)d_in[1];
    const float* sinb = (const float*)d_in[2];
    const float* Wq   = (const float*)d_in[3];
    const float* Wk   = (const float*)d_in[4];
    const float* Wv   = (const float*)d_in[5];
    const float* Wo   = (const float*)d_in[6];
    float* out = (float*)d_out;

    float *Q, *K, *V, *AO;
    cudaGetSymbolAddress((void**)&Q,  g_Q);
    cudaGetSymbolAddress((void**)&K,  g_K);
    cudaGetSymbolAddress((void**)&V,  g_V);
    cudaGetSymbolAddress((void**)&AO, g_AO);

    static bool attr_done = false;
    if (!attr_done) {
        cudaFuncSetAttribute(gemm_mma, cudaFuncAttributeMaxDynamicSharedMemorySize, SMEM_GEMM);
        cudaFuncSetAttribute(gemm_kv,  cudaFuncAttributeMaxDynamicSharedMemorySize, SMEM_GEMM);
        cudaFuncSetAttribute(attn_mma_kernel, cudaFuncAttributeMaxDynamicSharedMemorySize, SMEM_ATTN);
        attr_done = true;
    }

    const int M = BATCH * SEQ;

    // Q projection
    gemm_mma<<<dim3(EMB / 128, M / 128), 256, SMEM_GEMM>>>(x, Wq, Q, M, NHEADS * HDIM, EMB);
    // K + V projections fused (z selects)
    gemm_kv<<<dim3((NKVH * HDIM) / 128, M / 128, 2), 256, SMEM_GEMM>>>(
        x, Wk, Wv, K, V, M, NKVH * HDIM, EMB);

    {
        int total = BATCH * SEQ * (NHEADS + NKVH) * (HDIM / 2);
        rope_kernel<<<(total + 255) / 256, 256>>>(cosb, sinb);
    }

    attn_mma_kernel<<<dim3(SEQ / 64, NHEADS, BATCH), 128, SMEM_ATTN>>>();

    gemm_mma<<<dim3(EMB / 128, M / 128), 256, SMEM_GEMM>>>(AO, Wo, out, M, EMB, EMB);
}

// round 6
// speedup vs baseline: 4.8538x; 1.3541x over previous
#include <cuda_runtime.h>
#include <cstdint>
#include <math.h>

// Problem constants
constexpr int BATCH  = 2;
constexpr int SEQ    = 2048;
constexpr int EMB    = 2048;
constexpr int NHEADS = 16;
constexpr int NKVH   = 4;
constexpr int HDIM   = 128;
constexpr int WIN    = 1024;
constexpr int GQA    = NHEADS / NKVH;

// fp32 scratch
__device__ __align__(16) float g_Q [BATCH * SEQ * NHEADS * HDIM];
__device__ __align__(16) float g_K [BATCH * SEQ * NKVH   * HDIM];
__device__ __align__(16) float g_V [BATCH * SEQ * NKVH   * HDIM];
// tf32 (u32) scratch
__device__ __align__(16) uint32_t g_xt [BATCH * SEQ * EMB];
__device__ __align__(16) uint32_t g_Wqt[EMB * EMB];
__device__ __align__(16) uint32_t g_Wkt[NKVH * HDIM * EMB];
__device__ __align__(16) uint32_t g_Wvt[NKVH * HDIM * EMB];
__device__ __align__(16) uint32_t g_Wot[EMB * EMB];
__device__ __align__(16) uint32_t g_AOt[BATCH * SEQ * EMB];

__device__ __forceinline__ uint32_t f2tf32(float x) {
    uint32_t r;
    asm("cvt.rna.tf32.f32 %0, %1;" : "=r"(r) : "f"(x));
    return r;
}
__device__ __forceinline__ float ex2(float x) {
    float r;
    asm("ex2.approx.f32 %0, %1;" : "=f"(r) : "f"(x));
    return r;
}
__device__ __forceinline__ void mma_tf32(
    float& d0, float& d1, float& d2, float& d3,
    uint32_t a0, uint32_t a1, uint32_t a2, uint32_t a3,
    uint32_t b0, uint32_t b1)
{
    asm volatile(
        "mma.sync.aligned.m16n8k8.row.col.f32.tf32.tf32.f32 "
        "{%0,%1,%2,%3}, {%4,%5,%6,%7}, {%8,%9}, {%0,%1,%2,%3};"
        : "+f"(d0), "+f"(d1), "+f"(d2), "+f"(d3)
        : "r"(a0), "r"(a1), "r"(a2), "r"(a3), "r"(b0), "r"(b1));
}
__device__ __forceinline__ void cp16(uint32_t saddr, const void* gptr) {
    asm volatile("cp.async.cg.shared.global [%0], [%1], 16;"
                 :: "r"(saddr), "l"(gptr));
}

// ---------------------------------------------------------------------------
// fp32 -> tf32 bulk convert
// ---------------------------------------------------------------------------
__global__ void cvt_tf32_kernel(const float4* __restrict__ src,
                                uint4* __restrict__ dst, int n4)
{
    int i = blockIdx.x * blockDim.x + threadIdx.x;
    if (i >= n4) return;
    float4 v = src[i];
    dst[i] = make_uint4(f2tf32(v.x), f2tf32(v.y), f2tf32(v.z), f2tf32(v.w));
}

// ===========================================================================
// TF32 GEMM, pre-converted operands, cp.async pipeline.
// C[M,N] = A[M,K] * B[N,K]^T ; A,B are tf32-in-u32, C fp32.
// 128x128x32 tile, 256 threads, 8 warps (2x4), warp tile 64x32.
// ===========================================================================
constexpr int BM = 128, BN = 128, BKC = 32;
constexpr int SAPAD = 36;
constexpr int TILE_U32 = BM * SAPAD;                  // 4608
constexpr int SMEM_GEMM = 2 * 2 * TILE_U32 * 4;       // 73728 bytes

__device__ __forceinline__ void gemm_body(
    const uint32_t* __restrict__ A, const uint32_t* __restrict__ B,
    float* __restrict__ C, int M, int N, int K,
    int bx, int by, uint32_t* smem)
{
    const int tid  = threadIdx.x;
    const int lane = tid & 31;
    const int wid  = tid >> 5;
    const int m0 = by * BM;
    const int n0 = bx * BN;

    const int wm  = (wid >> 2) * 64;
    const int wn  = (wid & 3) * 32;
    const int gID = lane >> 2;
    const int tig = lane & 3;

    const int lr0 = tid >> 3;     // 0..31 (+32*j)
    const int lc4 = tid & 7;      // float4 col

    const uint32_t* Abase = A + (size_t)(m0 + lr0) * K + lc4 * 4;
    const uint32_t* Bbase = B + (size_t)(n0 + lr0) * K + lc4 * 4;
    const uint32_t sbase = (uint32_t)__cvta_generic_to_shared(smem);

    float acc[4][4][4];
#pragma unroll
    for (int mi = 0; mi < 4; ++mi)
#pragma unroll
        for (int ni = 0; ni < 4; ++ni)
#pragma unroll
            for (int q = 0; q < 4; ++q) acc[mi][ni][q] = 0.f;

    const int nch = K / BKC;

    // issue stage for chunk c into buffer c&1
    auto issue = [&](int c) {
        const uint32_t st = sbase + (uint32_t)((c & 1) * 2 * TILE_U32) * 4;
        const int kb = c * BKC;
#pragma unroll
        for (int j = 0; j < 4; ++j) {
            int r = lr0 + 32 * j;
            cp16(st + (uint32_t)(r * SAPAD + lc4 * 4) * 4,
                 Abase + (size_t)(32 * j) * K + kb);
            cp16(st + (uint32_t)(TILE_U32 + r * SAPAD + lc4 * 4) * 4,
                 Bbase + (size_t)(32 * j) * K + kb);
        }
        asm volatile("cp.async.commit_group;");
    };

    issue(0);

    for (int c = 0; c < nch; ++c) {
        if (c + 1 < nch) {
            issue(c + 1);
            asm volatile("cp.async.wait_group 1;");
        } else {
            asm volatile("cp.async.wait_group 0;");
        }
        __syncthreads();

        const uint32_t* sA = smem + (c & 1) * 2 * TILE_U32;
        const uint32_t* sB = sA + TILE_U32;
#pragma unroll
        for (int ks = 0; ks < 4; ++ks) {
            const int kq = ks * 8;
            uint32_t af[4][4], bf[4][2];
#pragma unroll
            for (int mi = 0; mi < 4; ++mi) {
                int row = wm + mi * 16 + gID;
                af[mi][0] = sA[row * SAPAD + kq + tig];
                af[mi][1] = sA[(row + 8) * SAPAD + kq + tig];
                af[mi][2] = sA[row * SAPAD + kq + tig + 4];
                af[mi][3] = sA[(row + 8) * SAPAD + kq + tig + 4];
            }
#pragma unroll
            for (int ni = 0; ni < 4; ++ni) {
                int col = wn + ni * 8 + gID;
                bf[ni][0] = sB[col * SAPAD + kq + tig];
                bf[ni][1] = sB[col * SAPAD + kq + tig + 4];
            }
#pragma unroll
            for (int mi = 0; mi < 4; ++mi)
#pragma unroll
                for (int ni = 0; ni < 4; ++ni)
                    mma_tf32(acc[mi][ni][0], acc[mi][ni][1], acc[mi][ni][2], acc[mi][ni][3],
                             af[mi][0], af[mi][1], af[mi][2], af[mi][3],
                             bf[ni][0], bf[ni][1]);
        }
        __syncthreads();
    }

#pragma unroll
    for (int mi = 0; mi < 4; ++mi) {
        int row = m0 + wm + mi * 16 + gID;
#pragma unroll
        for (int ni = 0; ni < 4; ++ni) {
            int col = n0 + wn + ni * 8 + tig * 2;
            *reinterpret_cast<float2*>(C + (size_t)row * N + col) =
                make_float2(acc[mi][ni][0], acc[mi][ni][1]);
            *reinterpret_cast<float2*>(C + (size_t)(row + 8) * N + col) =
                make_float2(acc[mi][ni][2], acc[mi][ni][3]);
        }
    }
}

__global__ __launch_bounds__(256, 2) void gemm_mma(
    const uint32_t* __restrict__ A, const uint32_t* __restrict__ B,
    float* __restrict__ C, int M, int N, int K)
{
    extern __shared__ uint32_t smem[];
    gemm_body(A, B, C, M, N, K, blockIdx.x, blockIdx.y, smem);
}

__global__ __launch_bounds__(256, 2) void gemm_kv(
    const uint32_t* __restrict__ A,
    const uint32_t* __restrict__ Wk, const uint32_t* __restrict__ Wv,
    float* __restrict__ Kout, float* __restrict__ Vout,
    int M, int N, int K)
{
    extern __shared__ uint32_t smem[];
    const uint32_t* B = (blockIdx.z == 0) ? Wk : Wv;
    float* C          = (blockIdx.z == 0) ? Kout : Vout;
    gemm_body(A, B, C, M, N, K, blockIdx.x, blockIdx.y, smem);
}

// ---------------------------------------------------------------------------
// RoPE
// ---------------------------------------------------------------------------
__global__ void rope_kernel(const float* __restrict__ cosb,
                            const float* __restrict__ sinb)
{
    const int total = BATCH * SEQ * (NHEADS + NKVH) * (HDIM / 2);
    int idx = blockIdx.x * blockDim.x + threadIdx.x;
    if (idx >= total) return;
    int d    = idx & 63;
    int rest = idx >> 6;
    int slot = rest % (NHEADS + NKVH);
    int bs   = rest / (NHEADS + NKVH);
    int s    = bs % SEQ;

    float c0 = cosb[s * HDIM + d];
    float c1 = cosb[s * HDIM + d + 64];
    float s0 = sinb[s * HDIM + d];
    float s1 = sinb[s * HDIM + d + 64];

    float* p;
    if (slot < NHEADS) p = g_Q + (bs * NHEADS + slot) * HDIM;
    else               p = g_K + (bs * NKVH + (slot - NHEADS)) * HDIM;

    float x0 = p[d], x1 = p[d + 64];
    p[d]      = x0 * c0 - x1 * s0;
    p[d + 64] = x1 * c1 + x0 * s1;
}

// ===========================================================================
// TF32 MMA flash attention, sliding window, GQA, exp2 softmax.
// Output written tf32 (u32) directly to g_AOt for the O-projection.
// ===========================================================================
constexpr int KSTRIDE = 132;
constexpr int VSTRIDE = 136;
constexpr int QSTRIDE = 132;
constexpr int PSTRIDE = 36;

constexpr int KS_OFF = 0;
constexpr int VS_OFF = KS_OFF + 32 * KSTRIDE;
constexpr int QP_OFF = VS_OFF + 32 * VSTRIDE;
constexpr int SMEM_ATTN = (QP_OFF + 64 * QSTRIDE) * 4;

__global__ __launch_bounds__(128) void attn_mma_kernel()
{
    extern __shared__ uint32_t sm[];

    const int tid  = threadIdx.x;
    const int lane = tid & 31;
    const int wq   = tid >> 5;
    const int g    = lane >> 2;
    const int t    = lane & 3;

    const int q0  = blockIdx.x * 64;
    const int h   = blockIdx.y;
    const int b   = blockIdx.z;
    const int kvh = h / GQA;
    const int bS  = b * SEQ;
    const int qw  = q0 + wq * 16;

    const float scale = 0.08838834764831845f * 1.4426950408889634f;

    {
        const float* Qg = g_Q + ((size_t)(bS + q0) * NHEADS + h) * HDIM;
#pragma unroll
        for (int i = tid; i < 2048; i += 128) {
            int r  = i >> 5;
            int c4 = i & 31;
            float4 v = *reinterpret_cast<const float4*>(Qg + (size_t)r * NHEADS * HDIM + c4 * 4);
            *reinterpret_cast<uint4*>(&sm[QP_OFF + r * QSTRIDE + c4 * 4]) =
                make_uint4(f2tf32(v.x * scale), f2tf32(v.y * scale),
                           f2tf32(v.z * scale), f2tf32(v.w * scale));
        }
    }
    __syncthreads();

    uint32_t qf[16][4];
#pragma unroll
    for (int kk = 0; kk < 16; ++kk) {
        int r0 = (wq * 16 + g) * QSTRIDE + kk * 8 + t;
        qf[kk][0] = sm[QP_OFF + r0];
        qf[kk][1] = sm[QP_OFF + r0 + 8 * QSTRIDE];
        qf[kk][2] = sm[QP_OFF + r0 + 4];
        qf[kk][3] = sm[QP_OFF + r0 + 8 * QSTRIDE + 4];
    }
    __syncthreads();

    uint32_t* Pw = &sm[QP_OFF + wq * 1024];

    float m0r = -1e30f, m1r = -1e30f, l0 = 0.f, l1 = 0.f;
    float oacc[16][4];
#pragma unroll
    for (int ni = 0; ni < 16; ++ni)
#pragma unroll
        for (int qd = 0; qd < 4; ++qd) oacc[ni][qd] = 0.f;

    int jstart = q0 - (WIN - 1);
    if (jstart < 0) jstart = 0;
    jstart &= ~31;

    for (int j0 = jstart; j0 < q0 + 64; j0 += 32) {
        __syncthreads();
        {
            const float* Kg = g_K + ((size_t)(bS + j0) * NKVH + kvh) * HDIM;
            const float* Vg = g_V + ((size_t)(bS + j0) * NKVH + kvh) * HDIM;
#pragma unroll
            for (int i = tid; i < 1024; i += 128) {
                int r  = i >> 5;
                int c4 = i & 31;
                size_t goff = (size_t)r * NKVH * HDIM + c4 * 4;
                float4 kv = *reinterpret_cast<const float4*>(Kg + goff);
                float4 vv = *reinterpret_cast<const float4*>(Vg + goff);
                *reinterpret_cast<uint4*>(&sm[KS_OFF + r * KSTRIDE + c4 * 4]) =
                    make_uint4(f2tf32(kv.x), f2tf32(kv.y), f2tf32(kv.z), f2tf32(kv.w));
                *reinterpret_cast<uint4*>(&sm[VS_OFF + r * VSTRIDE + c4 * 4]) =
                    make_uint4(f2tf32(vv.x), f2tf32(vv.y), f2tf32(vv.z), f2tf32(vv.w));
            }
        }
        __syncthreads();

        if (j0 > qw + 15) continue;
        if (qw - (j0 + 31) >= WIN) continue;

        float sc[4][4];
#pragma unroll
        for (int ni = 0; ni < 4; ++ni)
#pragma unroll
            for (int qd = 0; qd < 4; ++qd) sc[ni][qd] = 0.f;

#pragma unroll
        for (int kk = 0; kk < 16; ++kk) {
#pragma unroll
            for (int ni = 0; ni < 4; ++ni) {
                uint32_t b0 = sm[KS_OFF + (ni * 8 + g) * KSTRIDE + kk * 8 + t];
                uint32_t b1 = sm[KS_OFF + (ni * 8 + g) * KSTRIDE + kk * 8 + t + 4];
                mma_tf32(sc[ni][0], sc[ni][1], sc[ni][2], sc[ni][3],
                         qf[kk][0], qf[kk][1], qf[kk][2], qf[kk][3], b0, b1);
            }
        }

        const int r0 = qw + g;
        float tmax0 = -1e30f, tmax1 = -1e30f;
#pragma unroll
        for (int ni = 0; ni < 4; ++ni) {
            int col0 = j0 + ni * 8 + 2 * t;
#pragma unroll
            for (int cc = 0; cc < 2; ++cc) {
                int col = col0 + cc;
                int d0 = r0 - col;
                int d1 = r0 + 8 - col;
                if (!(d0 >= 0 && d0 < WIN)) sc[ni][cc]     = -1e30f;
                if (!(d1 >= 0 && d1 < WIN)) sc[ni][cc + 2] = -1e30f;
                tmax0 = fmaxf(tmax0, sc[ni][cc]);
                tmax1 = fmaxf(tmax1, sc[ni][cc + 2]);
            }
        }
        tmax0 = fmaxf(tmax0, __shfl_xor_sync(0xffffffffu, tmax0, 1));
        tmax0 = fmaxf(tmax0, __shfl_xor_sync(0xffffffffu, tmax0, 2));
        tmax1 = fmaxf(tmax1, __shfl_xor_sync(0xffffffffu, tmax1, 1));
        tmax1 = fmaxf(tmax1, __shfl_xor_sync(0xffffffffu, tmax1, 2));

        float mn0 = fmaxf(m0r, tmax0);
        float mn1 = fmaxf(m1r, tmax1);
        float cor0 = ex2(m0r - mn0);
        float cor1 = ex2(m1r - mn1);
        m0r = mn0; m1r = mn1;

        float ps0 = 0.f, ps1 = 0.f;
#pragma unroll
        for (int ni = 0; ni < 4; ++ni) {
#pragma unroll
            for (int cc = 0; cc < 2; ++cc) {
                float p0 = (sc[ni][cc]     > -1e29f) ? ex2(sc[ni][cc]     - mn0) : 0.f;
                float p1 = (sc[ni][cc + 2] > -1e29f) ? ex2(sc[ni][cc + 2] - mn1) : 0.f;
                ps0 += p0; ps1 += p1;
                int colL = ni * 8 + 2 * t + cc;
                Pw[g * PSTRIDE + colL]       = f2tf32(p0);
                Pw[(g + 8) * PSTRIDE + colL] = f2tf32(p1);
            }
        }
        ps0 += __shfl_xor_sync(0xffffffffu, ps0, 1);
        ps0 += __shfl_xor_sync(0xffffffffu, ps0, 2);
        ps1 += __shfl_xor_sync(0xffffffffu, ps1, 1);
        ps1 += __shfl_xor_sync(0xffffffffu, ps1, 2);
        l0 = l0 * cor0 + ps0;
        l1 = l1 * cor1 + ps1;

#pragma unroll
        for (int ni = 0; ni < 16; ++ni) {
            oacc[ni][0] *= cor0; oacc[ni][1] *= cor0;
            oacc[ni][2] *= cor1; oacc[ni][3] *= cor1;
        }

        __syncwarp();

#pragma unroll
        for (int kc = 0; kc < 4; ++kc) {
            uint32_t a0 = Pw[g * PSTRIDE + kc * 8 + t];
            uint32_t a1 = Pw[(g + 8) * PSTRIDE + kc * 8 + t];
            uint32_t a2 = Pw[g * PSTRIDE + kc * 8 + t + 4];
            uint32_t a3 = Pw[(g + 8) * PSTRIDE + kc * 8 + t + 4];
#pragma unroll
            for (int ni = 0; ni < 16; ++ni) {
                uint32_t b0 = sm[VS_OFF + (kc * 8 + t) * VSTRIDE + ni * 8 + g];
                uint32_t b1 = sm[VS_OFF + (kc * 8 + t + 4) * VSTRIDE + ni * 8 + g];
                mma_tf32(oacc[ni][0], oacc[ni][1], oacc[ni][2], oacc[ni][3],
                         a0, a1, a2, a3, b0, b1);
            }
        }
        __syncwarp();
    }

    // normalize + store tf32 for the O-projection
    float inv0 = 1.f / l0;
    float inv1 = 1.f / l1;
    uint32_t* Ot  = g_AOt + ((size_t)(bS + qw + g) * NHEADS + h) * HDIM;
    uint32_t* Ot8 = Ot + (size_t)8 * NHEADS * HDIM;
#pragma unroll
    for (int ni = 0; ni < 16; ++ni) {
        int col = ni * 8 + 2 * t;
        *reinterpret_cast<uint2*>(Ot + col) =
            make_uint2(f2tf32(oacc[ni][0] * inv0), f2tf32(oacc[ni][1] * inv0));
        *reinterpret_cast<uint2*>(Ot8 + col) =
            make_uint2(f2tf32(oacc[ni][2] * inv1), f2tf32(oacc[ni][3] * inv1));
    }
}

// ---------------------------------------------------------------------------
// Launch
// ---------------------------------------------------------------------------
extern "C" void kernel_launch(void* const* d_in, const int* in_sizes, int n_in,
                              void* d_out, int out_size)
{
    const float* x    = (const float*)d_in[0];
    const float* cosb = (const float*)d_in[1];
    const float* sinb = (const float*)d_in[2];
    const float* Wq   = (const float*)d_in[3];
    const float* Wk   = (const float*)d_in[4];
    const float* Wv   = (const float*)d_in[5];
    const float* Wo   = (const float*)d_in[6];
    float* out = (float*)d_out;

    float *Q, *K, *V;
    uint32_t *xt, *Wqt, *Wkt, *Wvt, *Wot, *AOt;
    cudaGetSymbolAddress((void**)&Q,   g_Q);
    cudaGetSymbolAddress((void**)&K,   g_K);
    cudaGetSymbolAddress((void**)&V,   g_V);
    cudaGetSymbolAddress((void**)&xt,  g_xt);
    cudaGetSymbolAddress((void**)&Wqt, g_Wqt);
    cudaGetSymbolAddress((void**)&Wkt, g_Wkt);
    cudaGetSymbolAddress((void**)&Wvt, g_Wvt);
    cudaGetSymbolAddress((void**)&Wot, g_Wot);
    cudaGetSymbolAddress((void**)&AOt, g_AOt);

    static bool attr_done = false;
    if (!attr_done) {
        cudaFuncSetAttribute(gemm_mma, cudaFuncAttributeMaxDynamicSharedMemorySize, SMEM_GEMM);
        cudaFuncSetAttribute(gemm_kv,  cudaFuncAttributeMaxDynamicSharedMemorySize, SMEM_GEMM);
        cudaFuncSetAttribute(attn_mma_kernel, cudaFuncAttributeMaxDynamicSharedMemorySize, SMEM_ATTN);
        attr_done = true;
    }

    const int M = BATCH * SEQ;

    // fp32 -> tf32 pre-conversion (one pass each)
    auto cvt = [](const float* s, uint32_t* d, int n) {
        int n4 = n / 4;
        cvt_tf32_kernel<<<(n4 + 255) / 256, 256>>>(
            reinterpret_cast<const float4*>(s), reinterpret_cast<uint4*>(d), n4);
    };
    cvt(x,  xt,  BATCH * SEQ * EMB);
    cvt(Wq, Wqt, EMB * EMB);
    cvt(Wk, Wkt, NKVH * HDIM * EMB);
    cvt(Wv, Wvt, NKVH * HDIM * EMB);
    cvt(Wo, Wot, EMB * EMB);

    // Q projection
    gemm_mma<<<dim3(EMB / 128, M / 128), 256, SMEM_GEMM>>>(xt, Wqt, Q, M, NHEADS * HDIM, EMB);
    // K + V projections fused
    gemm_kv<<<dim3((NKVH * HDIM) / 128, M / 128, 2), 256, SMEM_GEMM>>>(
        xt, Wkt, Wvt, K, V, M, NKVH * HDIM, EMB);

    {
        int total = BATCH * SEQ * (NHEADS + NKVH) * (HDIM / 2);
        rope_kernel<<<(total + 255) / 256, 256>>>(cosb, sinb);
    }

    attn_mma_kernel<<<dim3(SEQ / 64, NHEADS, BATCH), 128, SMEM_ATTN>>>();

    // Output projection (A = attention output already tf32)
    gemm_mma<<<dim3(EMB / 128, M / 128), 256, SMEM_GEMM>>>(AOt, Wot, out, M, EMB, EMB);
}

// round 7
// speedup vs baseline: 5.1033x; 1.0514x over previous
#include <cuda_runtime.h>
#include <cstdint>
#include <math.h>

// Problem constants
constexpr int BATCH  = 2;
constexpr int SEQ    = 2048;
constexpr int EMB    = 2048;
constexpr int NHEADS = 16;
constexpr int NKVH   = 4;
constexpr int HDIM   = 128;
constexpr int WIN    = 1024;
constexpr int GQA    = NHEADS / NKVH;

// fp32 scratch
__device__ __align__(16) float g_Q [BATCH * SEQ * NHEADS * HDIM];
__device__ __align__(16) float g_K [BATCH * SEQ * NKVH   * HDIM];
__device__ __align__(16) float g_V [BATCH * SEQ * NKVH   * HDIM];
// tf32 (u32) scratch
__device__ __align__(16) uint32_t g_xt [BATCH * SEQ * EMB];
__device__ __align__(16) uint32_t g_Wqt[EMB * EMB];
__device__ __align__(16) uint32_t g_Wkt[NKVH * HDIM * EMB];
__device__ __align__(16) uint32_t g_Wvt[NKVH * HDIM * EMB];
__device__ __align__(16) uint32_t g_Wot[EMB * EMB];
__device__ __align__(16) uint32_t g_AOt[BATCH * SEQ * EMB];

__device__ __forceinline__ uint32_t f2tf32(float x) {
    uint32_t r;
    asm("cvt.rna.tf32.f32 %0, %1;" : "=r"(r) : "f"(x));
    return r;
}
__device__ __forceinline__ float ex2(float x) {
    float r;
    asm("ex2.approx.f32 %0, %1;" : "=f"(r) : "f"(x));
    return r;
}
__device__ __forceinline__ void mma_tf32(
    float& d0, float& d1, float& d2, float& d3,
    uint32_t a0, uint32_t a1, uint32_t a2, uint32_t a3,
    uint32_t b0, uint32_t b1)
{
    asm volatile(
        "mma.sync.aligned.m16n8k8.row.col.f32.tf32.tf32.f32 "
        "{%0,%1,%2,%3}, {%4,%5,%6,%7}, {%8,%9}, {%0,%1,%2,%3};"
        : "+f"(d0), "+f"(d1), "+f"(d2), "+f"(d3)
        : "r"(a0), "r"(a1), "r"(a2), "r"(a3), "r"(b0), "r"(b1));
}
__device__ __forceinline__ void cp16(uint32_t saddr, const void* gptr) {
    asm volatile("cp.async.cg.shared.global [%0], [%1], 16;"
                 :: "r"(saddr), "l"(gptr));
}

// ---------------------------------------------------------------------------
// fp32 -> tf32 bulk convert
// ---------------------------------------------------------------------------
__global__ void cvt_tf32_kernel(const float4* __restrict__ src,
                                uint4* __restrict__ dst, int n4)
{
    int i = blockIdx.x * blockDim.x + threadIdx.x;
    if (i >= n4) return;
    float4 v = src[i];
    dst[i] = make_uint4(f2tf32(v.x), f2tf32(v.y), f2tf32(v.z), f2tf32(v.w));
}

// ===========================================================================
// TF32 GEMM, pre-converted operands, 3-stage cp.async pipeline.
// C[M,N] = A[M,K] * B[N,K]^T ; A,B tf32-in-u32, C fp32.
// 128x128x32 tile, 256 threads, 8 warps (2x4), warp tile 64x32.
// ===========================================================================
constexpr int BM = 128, BN = 128, BKC = 32;
constexpr int SAPAD = 36;
constexpr int TILE_U32 = BM * SAPAD;                     // 4608
constexpr int NSTG = 3;
constexpr int SMEM_GEMM = NSTG * 2 * TILE_U32 * 4;       // 110592 bytes

__device__ __forceinline__ void gemm_body(
    const uint32_t* __restrict__ A, const uint32_t* __restrict__ B,
    float* __restrict__ C, int M, int N, int K,
    int bx, int by, uint32_t* smem)
{
    const int tid  = threadIdx.x;
    const int lane = tid & 31;
    const int wid  = tid >> 5;
    const int m0 = by * BM;
    const int n0 = bx * BN;

    const int wm  = (wid >> 2) * 64;
    const int wn  = (wid & 3) * 32;
    const int gID = lane >> 2;
    const int tig = lane & 3;

    const int lr0 = tid >> 3;
    const int lc4 = tid & 7;

    const uint32_t* Abase = A + (size_t)(m0 + lr0) * K + lc4 * 4;
    const uint32_t* Bbase = B + (size_t)(n0 + lr0) * K + lc4 * 4;
    const uint32_t sbase = (uint32_t)__cvta_generic_to_shared(smem);

    float acc[4][4][4];
#pragma unroll
    for (int mi = 0; mi < 4; ++mi)
#pragma unroll
        for (int ni = 0; ni < 4; ++ni)
#pragma unroll
            for (int q = 0; q < 4; ++q) acc[mi][ni][q] = 0.f;

    const int nch = K / BKC;

    auto issue = [&](int c) {
        const uint32_t st = sbase + (uint32_t)((c % NSTG) * 2 * TILE_U32) * 4;
        const int kb = c * BKC;
#pragma unroll
        for (int j = 0; j < 4; ++j) {
            int r = lr0 + 32 * j;
            cp16(st + (uint32_t)(r * SAPAD + lc4 * 4) * 4,
                 Abase + (size_t)(32 * j) * K + kb);
            cp16(st + (uint32_t)(TILE_U32 + r * SAPAD + lc4 * 4) * 4,
                 Bbase + (size_t)(32 * j) * K + kb);
        }
        asm volatile("cp.async.commit_group;");
    };

    issue(0);
    issue(1);

    for (int c = 0; c < nch; ++c) {
        if (c + 1 < nch) asm volatile("cp.async.wait_group 1;");
        else             asm volatile("cp.async.wait_group 0;");
        __syncthreads();

        const uint32_t* sA = smem + (c % NSTG) * 2 * TILE_U32;
        const uint32_t* sB = sA + TILE_U32;
#pragma unroll
        for (int ks = 0; ks < 4; ++ks) {
            const int kq = ks * 8;
            uint32_t af[4][4], bf[4][2];
#pragma unroll
            for (int mi = 0; mi < 4; ++mi) {
                int row = wm + mi * 16 + gID;
                af[mi][0] = sA[row * SAPAD + kq + tig];
                af[mi][1] = sA[(row + 8) * SAPAD + kq + tig];
                af[mi][2] = sA[row * SAPAD + kq + tig + 4];
                af[mi][3] = sA[(row + 8) * SAPAD + kq + tig + 4];
            }
#pragma unroll
            for (int ni = 0; ni < 4; ++ni) {
                int col = wn + ni * 8 + gID;
                bf[ni][0] = sB[col * SAPAD + kq + tig];
                bf[ni][1] = sB[col * SAPAD + kq + tig + 4];
            }
#pragma unroll
            for (int mi = 0; mi < 4; ++mi)
#pragma unroll
                for (int ni = 0; ni < 4; ++ni)
                    mma_tf32(acc[mi][ni][0], acc[mi][ni][1], acc[mi][ni][2], acc[mi][ni][3],
                             af[mi][0], af[mi][1], af[mi][2], af[mi][3],
                             bf[ni][0], bf[ni][1]);
        }

        if (c + 2 < nch) issue(c + 2);
    }

#pragma unroll
    for (int mi = 0; mi < 4; ++mi) {
        int row = m0 + wm + mi * 16 + gID;
#pragma unroll
        for (int ni = 0; ni < 4; ++ni) {
            int col = n0 + wn + ni * 8 + tig * 2;
            *reinterpret_cast<float2*>(C + (size_t)row * N + col) =
                make_float2(acc[mi][ni][0], acc[mi][ni][1]);
            *reinterpret_cast<float2*>(C + (size_t)(row + 8) * N + col) =
                make_float2(acc[mi][ni][2], acc[mi][ni][3]);
        }
    }
}

__global__ __launch_bounds__(256, 2) void gemm_mma(
    const uint32_t* __restrict__ A, const uint32_t* __restrict__ B,
    float* __restrict__ C, int M, int N, int K)
{
    extern __shared__ uint32_t smem[];
    gemm_body(A, B, C, M, N, K, blockIdx.x, blockIdx.y, smem);
}

__global__ __launch_bounds__(256, 2) void gemm_kv(
    const uint32_t* __restrict__ A,
    const uint32_t* __restrict__ Wk, const uint32_t* __restrict__ Wv,
    float* __restrict__ Kout, float* __restrict__ Vout,
    int M, int N, int K)
{
    extern __shared__ uint32_t smem[];
    const uint32_t* B = (blockIdx.z == 0) ? Wk : Wv;
    float* C          = (blockIdx.z == 0) ? Kout : Vout;
    gemm_body(A, B, C, M, N, K, blockIdx.x, blockIdx.y, smem);
}

// ---------------------------------------------------------------------------
// RoPE
// ---------------------------------------------------------------------------
__global__ void rope_kernel(const float* __restrict__ cosb,
                            const float* __restrict__ sinb)
{
    const int total = BATCH * SEQ * (NHEADS + NKVH) * (HDIM / 2);
    int idx = blockIdx.x * blockDim.x + threadIdx.x;
    if (idx >= total) return;
    int d    = idx & 63;
    int rest = idx >> 6;
    int slot = rest % (NHEADS + NKVH);
    int bs   = rest / (NHEADS + NKVH);
    int s    = bs % SEQ;

    float c0 = cosb[s * HDIM + d];
    float c1 = cosb[s * HDIM + d + 64];
    float s0 = sinb[s * HDIM + d];
    float s1 = sinb[s * HDIM + d + 64];

    float* p;
    if (slot < NHEADS) p = g_Q + (bs * NHEADS + slot) * HDIM;
    else               p = g_K + (bs * NKVH + (slot - NHEADS)) * HDIM;

    float x0 = p[d], x1 = p[d + 64];
    p[d]      = x0 * c0 - x1 * s0;
    p[d + 64] = x1 * c1 + x0 * s1;
}

// ===========================================================================
// TF32 MMA flash attention: GQA-shared KV staging.
// CTA = 4 heads x 32 queries (256 threads, 8 warps).
// warp w: head_local = w>>1, rows = q0 + (w&1)*16 .. +16.
// K/V tiles staged ONCE per CTA for all 4 heads.
// ===========================================================================
constexpr int KSTRIDE = 132;
constexpr int VSTRIDE = 136;
constexpr int QSTRIDE = 132;
constexpr int PSTRIDE = 36;

constexpr int KS_OFF = 0;                        // 32*132 = 4224
constexpr int VS_OFF = KS_OFF + 32 * KSTRIDE;    // 4224
constexpr int QP_OFF = VS_OFF + 32 * VSTRIDE;    // 8576; Q 128*132=16896, P 8*1024
constexpr int SMEM_ATTN = (QP_OFF + 128 * QSTRIDE) * 4;   // 101888 bytes

__global__ __launch_bounds__(256, 1) void attn_mma_kernel()
{
    extern __shared__ uint32_t sm[];

    const int tid  = threadIdx.x;
    const int lane = tid & 31;
    const int wid  = tid >> 5;
    const int hl   = wid >> 1;          // head within GQA group
    const int sub  = wid & 1;           // 16-row half
    const int g    = lane >> 2;
    const int t    = lane & 3;

    const int q0  = blockIdx.x * 32;
    const int kvh = blockIdx.y;
    const int b   = blockIdx.z;
    const int h   = kvh * GQA + hl;
    const int bS  = b * SEQ;
    const int qw  = q0 + sub * 16;

    const float scale = 0.08838834764831845f * 1.4426950408889634f;

    // ---- stage Q for all 4 heads (scaled, tf32) ----
#pragma unroll
    for (int i = tid; i < 4096; i += 256) {
        int ih = i >> 10;          // head
        int r  = (i >> 5) & 31;    // row
        int c4 = i & 31;
        const float* src = g_Q +
            ((size_t)(bS + q0 + r) * NHEADS + kvh * GQA + ih) * HDIM + c4 * 4;
        float4 v = *reinterpret_cast<const float4*>(src);
        *reinterpret_cast<uint4*>(&sm[QP_OFF + (ih * 32 + r) * QSTRIDE + c4 * 4]) =
            make_uint4(f2tf32(v.x * scale), f2tf32(v.y * scale),
                       f2tf32(v.z * scale), f2tf32(v.w * scale));
    }
    __syncthreads();

    uint32_t qf[16][4];
#pragma unroll
    for (int kk = 0; kk < 16; ++kk) {
        int r0 = (hl * 32 + sub * 16 + g) * QSTRIDE + kk * 8 + t;
        qf[kk][0] = sm[QP_OFF + r0];
        qf[kk][1] = sm[QP_OFF + r0 + 8 * QSTRIDE];
        qf[kk][2] = sm[QP_OFF + r0 + 4];
        qf[kk][3] = sm[QP_OFF + r0 + 8 * QSTRIDE + 4];
    }
    __syncthreads();   // Q region now reusable as P scratch

    uint32_t* Pw = &sm[QP_OFF + wid * 1024];

    float m0r = -1e30f, m1r = -1e30f, l0 = 0.f, l1 = 0.f;
    float oacc[16][4];
#pragma unroll
    for (int ni = 0; ni < 16; ++ni)
#pragma unroll
        for (int qd = 0; qd < 4; ++qd) oacc[ni][qd] = 0.f;

    int jstart = q0 - (WIN - 1);
    if (jstart < 0) jstart = 0;
    jstart &= ~31;

    for (int j0 = jstart; j0 < q0 + 32; j0 += 32) {
        __syncthreads();
        {
            const float* Kg = g_K + ((size_t)(bS + j0) * NKVH + kvh) * HDIM;
            const float* Vg = g_V + ((size_t)(bS + j0) * NKVH + kvh) * HDIM;
#pragma unroll
            for (int i = tid; i < 1024; i += 256) {
                int r  = i >> 5;
                int c4 = i & 31;
                size_t goff = (size_t)r * NKVH * HDIM + c4 * 4;
                float4 kv = *reinterpret_cast<const float4*>(Kg + goff);
                float4 vv = *reinterpret_cast<const float4*>(Vg + goff);
                *reinterpret_cast<uint4*>(&sm[KS_OFF + r * KSTRIDE + c4 * 4]) =
                    make_uint4(f2tf32(kv.x), f2tf32(kv.y), f2tf32(kv.z), f2tf32(kv.w));
                *reinterpret_cast<uint4*>(&sm[VS_OFF + r * VSTRIDE + c4 * 4]) =
                    make_uint4(f2tf32(vv.x), f2tf32(vv.y), f2tf32(vv.z), f2tf32(vv.w));
            }
        }
        __syncthreads();

        if (j0 > qw + 15) continue;
        if (qw - (j0 + 31) >= WIN) continue;

        float sc[4][4];
#pragma unroll
        for (int ni = 0; ni < 4; ++ni)
#pragma unroll
            for (int qd = 0; qd < 4; ++qd) sc[ni][qd] = 0.f;

#pragma unroll
        for (int kk = 0; kk < 16; ++kk) {
#pragma unroll
            for (int ni = 0; ni < 4; ++ni) {
                uint32_t b0 = sm[KS_OFF + (ni * 8 + g) * KSTRIDE + kk * 8 + t];
                uint32_t b1 = sm[KS_OFF + (ni * 8 + g) * KSTRIDE + kk * 8 + t + 4];
                mma_tf32(sc[ni][0], sc[ni][1], sc[ni][2], sc[ni][3],
                         qf[kk][0], qf[kk][1], qf[kk][2], qf[kk][3], b0, b1);
            }
        }

        const int r0 = qw + g;
        float tmax0 = -1e30f, tmax1 = -1e30f;
#pragma unroll
        for (int ni = 0; ni < 4; ++ni) {
            int col0 = j0 + ni * 8 + 2 * t;
#pragma unroll
            for (int cc = 0; cc < 2; ++cc) {
                int col = col0 + cc;
                int d0 = r0 - col;
                int d1 = r0 + 8 - col;
                if (!(d0 >= 0 && d0 < WIN)) sc[ni][cc]     = -1e30f;
                if (!(d1 >= 0 && d1 < WIN)) sc[ni][cc + 2] = -1e30f;
                tmax0 = fmaxf(tmax0, sc[ni][cc]);
                tmax1 = fmaxf(tmax1, sc[ni][cc + 2]);
            }
        }
        tmax0 = fmaxf(tmax0, __shfl_xor_sync(0xffffffffu, tmax0, 1));
        tmax0 = fmaxf(tmax0, __shfl_xor_sync(0xffffffffu, tmax0, 2));
        tmax1 = fmaxf(tmax1, __shfl_xor_sync(0xffffffffu, tmax1, 1));
        tmax1 = fmaxf(tmax1, __shfl_xor_sync(0xffffffffu, tmax1, 2));

        float mn0 = fmaxf(m0r, tmax0);
        float mn1 = fmaxf(m1r, tmax1);
        float cor0 = ex2(m0r - mn0);
        float cor1 = ex2(m1r - mn1);
        m0r = mn0; m1r = mn1;

        float ps0 = 0.f, ps1 = 0.f;
#pragma unroll
        for (int ni = 0; ni < 4; ++ni) {
#pragma unroll
            for (int cc = 0; cc < 2; ++cc) {
                float p0 = (sc[ni][cc]     > -1e29f) ? ex2(sc[ni][cc]     - mn0) : 0.f;
                float p1 = (sc[ni][cc + 2] > -1e29f) ? ex2(sc[ni][cc + 2] - mn1) : 0.f;
                ps0 += p0; ps1 += p1;
                int colL = ni * 8 + 2 * t + cc;
                Pw[g * PSTRIDE + colL]       = f2tf32(p0);
                Pw[(g + 8) * PSTRIDE + colL] = f2tf32(p1);
            }
        }
        ps0 += __shfl_xor_sync(0xffffffffu, ps0, 1);
        ps0 += __shfl_xor_sync(0xffffffffu, ps0, 2);
        ps1 += __shfl_xor_sync(0xffffffffu, ps1, 1);
        ps1 += __shfl_xor_sync(0xffffffffu, ps1, 2);
        l0 = l0 * cor0 + ps0;
        l1 = l1 * cor1 + ps1;

#pragma unroll
        for (int ni = 0; ni < 16; ++ni) {
            oacc[ni][0] *= cor0; oacc[ni][1] *= cor0;
            oacc[ni][2] *= cor1; oacc[ni][3] *= cor1;
        }

        __syncwarp();

#pragma unroll
        for (int kc = 0; kc < 4; ++kc) {
            uint32_t a0 = Pw[g * PSTRIDE + kc * 8 + t];
            uint32_t a1 = Pw[(g + 8) * PSTRIDE + kc * 8 + t];
            uint32_t a2 = Pw[g * PSTRIDE + kc * 8 + t + 4];
            uint32_t a3 = Pw[(g + 8) * PSTRIDE + kc * 8 + t + 4];
#pragma unroll
            for (int ni = 0; ni < 16; ++ni) {
                uint32_t b0 = sm[VS_OFF + (kc * 8 + t) * VSTRIDE + ni * 8 + g];
                uint32_t b1 = sm[VS_OFF + (kc * 8 + t + 4) * VSTRIDE + ni * 8 + g];
                mma_tf32(oacc[ni][0], oacc[ni][1], oacc[ni][2], oacc[ni][3],
                         a0, a1, a2, a3, b0, b1);
            }
        }
        __syncwarp();
    }

    // normalize + store tf32 for the O-projection
    float inv0 = 1.f / l0;
    float inv1 = 1.f / l1;
    uint32_t* Ot  = g_AOt + ((size_t)(bS + qw + g) * NHEADS + h) * HDIM;
    uint32_t* Ot8 = Ot + (size_t)8 * NHEADS * HDIM;
#pragma unroll
    for (int ni = 0; ni < 16; ++ni) {
        int col = ni * 8 + 2 * t;
        *reinterpret_cast<uint2*>(Ot + col) =
            make_uint2(f2tf32(oacc[ni][0] * inv0), f2tf32(oacc[ni][1] * inv0));
        *reinterpret_cast<uint2*>(Ot8 + col) =
            make_uint2(f2tf32(oacc[ni][2] * inv1), f2tf32(oacc[ni][3] * inv1));
    }
}

// ---------------------------------------------------------------------------
// Launch
// ---------------------------------------------------------------------------
extern "C" void kernel_launch(void* const* d_in, const int* in_sizes, int n_in,
                              void* d_out, int out_size)
{
    const float* x    = (const float*)d_in[0];
    const float* cosb = (const float*)d_in[1];
    const float* sinb = (const float*)d_in[2];
    const float* Wq   = (const float*)d_in[3];
    const float* Wk   = (const float*)d_in[4];
    const float* Wv   = (const float*)d_in[5];
    const float* Wo   = (const float*)d_in[6];
    float* out = (float*)d_out;

    float *Q, *K, *V;
    uint32_t *xt, *Wqt, *Wkt, *Wvt, *Wot, *AOt;
    cudaGetSymbolAddress((void**)&Q,   g_Q);
    cudaGetSymbolAddress((void**)&K,   g_K);
    cudaGetSymbolAddress((void**)&V,   g_V);
    cudaGetSymbolAddress((void**)&xt,  g_xt);
    cudaGetSymbolAddress((void**)&Wqt, g_Wqt);
    cudaGetSymbolAddress((void**)&Wkt, g_Wkt);
    cudaGetSymbolAddress((void**)&Wvt, g_Wvt);
    cudaGetSymbolAddress((void**)&Wot, g_Wot);
    cudaGetSymbolAddress((void**)&AOt, g_AOt);

    static bool attr_done = false;
    if (!attr_done) {
        cudaFuncSetAttribute(gemm_mma, cudaFuncAttributeMaxDynamicSharedMemorySize, SMEM_GEMM);
        cudaFuncSetAttribute(gemm_kv,  cudaFuncAttributeMaxDynamicSharedMemorySize, SMEM_GEMM);
        cudaFuncSetAttribute(attn_mma_kernel, cudaFuncAttributeMaxDynamicSharedMemorySize, SMEM_ATTN);
        attr_done = true;
    }

    const int M = BATCH * SEQ;

    auto cvt = [](const float* s, uint32_t* d, int n) {
        int n4 = n / 4;
        cvt_tf32_kernel<<<(n4 + 255) / 256, 256>>>(
            reinterpret_cast<const float4*>(s), reinterpret_cast<uint4*>(d), n4);
    };
    cvt(x,  xt,  BATCH * SEQ * EMB);
    cvt(Wq, Wqt, EMB * EMB);
    cvt(Wk, Wkt, NKVH * HDIM * EMB);
    cvt(Wv, Wvt, NKVH * HDIM * EMB);
    cvt(Wo, Wot, EMB * EMB);

    gemm_mma<<<dim3(EMB / 128, M / 128), 256, SMEM_GEMM>>>(xt, Wqt, Q, M, NHEADS * HDIM, EMB);
    gemm_kv<<<dim3((NKVH * HDIM) / 128, M / 128, 2), 256, SMEM_GEMM>>>(
        xt, Wkt, Wvt, K, V, M, NKVH * HDIM, EMB);

    {
        int total = BATCH * SEQ * (NHEADS + NKVH) * (HDIM / 2);
        rope_kernel<<<(total + 255) / 256, 256>>>(cosb, sinb);
    }

    attn_mma_kernel<<<dim3(SEQ / 32, NKVH, BATCH), 256, SMEM_ATTN>>>();

    gemm_mma<<<dim3(EMB / 128, M / 128), 256, SMEM_GEMM>>>(AOt, Wot, out, M, EMB, EMB);
}

// round 8
// speedup vs baseline: 9.0121x; 1.7660x over previous
#include <cuda_runtime.h>
#include <cuda_fp16.h>
#include <cstdint>
#include <math.h>

// Problem constants
constexpr int BATCH  = 2;
constexpr int SEQ    = 2048;
constexpr int EMB    = 2048;
constexpr int NHEADS = 16;
constexpr int NKVH   = 4;
constexpr int HDIM   = 128;
constexpr int WIN    = 1024;
constexpr int GQA    = NHEADS / NKVH;

// fp32 scratch (pre-rope Q/K)
__device__ __align__(16) float g_Q [BATCH * SEQ * NHEADS * HDIM];
__device__ __align__(16) float g_K [BATCH * SEQ * NKVH   * HDIM];
// fp16 (half2-in-u32) scratch
__device__ __align__(16) uint32_t g_xh [BATCH * SEQ * (EMB / 2)];
__device__ __align__(16) uint32_t g_Wqh[EMB * (EMB / 2)];
__device__ __align__(16) uint32_t g_Wkh[NKVH * HDIM * (EMB / 2)];
__device__ __align__(16) uint32_t g_Wvh[NKVH * HDIM * (EMB / 2)];
__device__ __align__(16) uint32_t g_Woh[EMB * (EMB / 2)];
__device__ __align__(16) uint32_t g_Qh [BATCH * SEQ * NHEADS * (HDIM / 2)];  // pre-scaled
__device__ __align__(16) uint32_t g_Kh [BATCH * SEQ * NKVH   * (HDIM / 2)];
__device__ __align__(16) __half   g_Vth[BATCH * NKVH * HDIM * SEQ];          // [b][kvh][d][s]
__device__ __align__(16) uint32_t g_AOh[BATCH * SEQ * (EMB / 2)];

__device__ __forceinline__ uint32_t pack2(float lo, float hi) {
    uint32_t r;
    asm("cvt.rn.f16x2.f32 %0, %1, %2;" : "=r"(r) : "f"(hi), "f"(lo));
    return r;
}
__device__ __forceinline__ float ex2(float x) {
    float r;
    asm("ex2.approx.f32 %0, %1;" : "=f"(r) : "f"(x));
    return r;
}
__device__ __forceinline__ void mma_f16(
    float& d0, float& d1, float& d2, float& d3,
    uint32_t a0, uint32_t a1, uint32_t a2, uint32_t a3,
    uint32_t b0, uint32_t b1)
{
    asm volatile(
        "mma.sync.aligned.m16n8k16.row.col.f32.f16.f16.f32 "
        "{%0,%1,%2,%3}, {%4,%5,%6,%7}, {%8,%9}, {%0,%1,%2,%3};"
        : "+f"(d0), "+f"(d1), "+f"(d2), "+f"(d3)
        : "r"(a0), "r"(a1), "r"(a2), "r"(a3), "r"(b0), "r"(b1));
}
__device__ __forceinline__ void cp16(uint32_t saddr, const void* gptr) {
    asm volatile("cp.async.cg.shared.global [%0], [%1], 16;"
                 :: "r"(saddr), "l"(gptr));
}

// ---------------------------------------------------------------------------
// fp32 -> fp16x2 bulk convert
// ---------------------------------------------------------------------------
__global__ void cvt_h_kernel(const float4* __restrict__ src,
                             uint2* __restrict__ dst, int n4)
{
    int i = blockIdx.x * blockDim.x + threadIdx.x;
    if (i >= n4) return;
    float4 v = src[i];
    dst[i] = make_uint2(pack2(v.x, v.y), pack2(v.z, v.w));
}

// ===========================================================================
// FP16 GEMM (NT): C[M,N] = A[M,K] * B[N,K]^T ; A,B half2-in-u32, C fp32.
// 128x128 tile, BK=64 halfs, 3-stage cp.async, 256 threads, warp tile 64x32.
// VMODE=1: write C as fp16 transposed into Vt[b][kvh][d][s].
// ===========================================================================
constexpr int SAPADH = 36;                        // u32 row stride (32 data + 4 pad)
constexpr int TILE_H = 128 * SAPADH;              // 4608 u32
constexpr int NSTG = 3;
constexpr int SMEM_GEMM = NSTG * 2 * TILE_H * 4;  // 110592 B

template<int VMODE>
__device__ __forceinline__ void gemm_body_f16(
    const uint32_t* __restrict__ A, const uint32_t* __restrict__ B,
    float* __restrict__ C, __half* __restrict__ Vt,
    int M, int N, int K, int bx, int by, uint32_t* smem)
{
    const int K2 = K / 2;                 // u32 per row
    const int tid  = threadIdx.x;
    const int lane = tid & 31;
    const int wid  = tid >> 5;
    const int m0 = by * 128;
    const int n0 = bx * 128;

    const int wm  = (wid >> 2) * 64;
    const int wn  = (wid & 3) * 32;
    const int gID = lane >> 2;
    const int tig = lane & 3;

    const int lr0 = tid >> 3;             // 0..31 (+32 per j)
    const int lc4 = tid & 7;              // 16B chunk within 32-u32 row

    const uint32_t* Abase = A + (size_t)(m0 + lr0) * K2 + lc4 * 4;
    const uint32_t* Bbase = B + (size_t)(n0 + lr0) * K2 + lc4 * 4;
    const uint32_t sbase = (uint32_t)__cvta_generic_to_shared(smem);

    float acc[4][4][4];
#pragma unroll
    for (int mi = 0; mi < 4; ++mi)
#pragma unroll
        for (int ni = 0; ni < 4; ++ni)
#pragma unroll
            for (int q = 0; q < 4; ++q) acc[mi][ni][q] = 0.f;

    const int nch = K / 64;               // 64 halfs (32 u32) per chunk

    auto issue = [&](int c) {
        const uint32_t st = sbase + (uint32_t)((c % NSTG) * 2 * TILE_H) * 4;
        const int kb = c * 32;
#pragma unroll
        for (int j = 0; j < 4; ++j) {
            int r = lr0 + 32 * j;
            cp16(st + (uint32_t)(r * SAPADH + lc4 * 4) * 4,
                 Abase + (size_t)(32 * j) * K2 + kb);
            cp16(st + (uint32_t)(TILE_H + r * SAPADH + lc4 * 4) * 4,
                 Bbase + (size_t)(32 * j) * K2 + kb);
        }
        asm volatile("cp.async.commit_group;");
    };

    issue(0);
    issue(1);

    for (int c = 0; c < nch; ++c) {
        if (c + 1 < nch) asm volatile("cp.async.wait_group 1;");
        else             asm volatile("cp.async.wait_group 0;");
        __syncthreads();

        const uint32_t* sA = smem + (c % NSTG) * 2 * TILE_H;
        const uint32_t* sB = sA + TILE_H;
#pragma unroll
        for (int ks = 0; ks < 4; ++ks) {          // each ks = k16 (8 u32)
            const int kq = ks * 8;
            uint32_t af[4][4], bf[4][2];
#pragma unroll
            for (int mi = 0; mi < 4; ++mi) {
                int row = wm + mi * 16 + gID;
                af[mi][0] = sA[row * SAPADH + kq + tig];
                af[mi][1] = sA[(row + 8) * SAPADH + kq + tig];
                af[mi][2] = sA[row * SAPADH + kq + tig + 4];
                af[mi][3] = sA[(row + 8) * SAPADH + kq + tig + 4];
            }
#pragma unroll
            for (int ni = 0; ni < 4; ++ni) {
                int col = wn + ni * 8 + gID;
                bf[ni][0] = sB[col * SAPADH + kq + tig];
                bf[ni][1] = sB[col * SAPADH + kq + tig + 4];
            }
#pragma unroll
            for (int mi = 0; mi < 4; ++mi)
#pragma unroll
                for (int ni = 0; ni < 4; ++ni)
                    mma_f16(acc[mi][ni][0], acc[mi][ni][1], acc[mi][ni][2], acc[mi][ni][3],
                            af[mi][0], af[mi][1], af[mi][2], af[mi][3],
                            bf[ni][0], bf[ni][1]);
        }

        if (c + 2 < nch) issue(c + 2);
    }

    if (VMODE == 0) {
#pragma unroll
        for (int mi = 0; mi < 4; ++mi) {
            int row = m0 + wm + mi * 16 + gID;
#pragma unroll
            for (int ni = 0; ni < 4; ++ni) {
                int col = n0 + wn + ni * 8 + tig * 2;
                *reinterpret_cast<float2*>(C + (size_t)row * N + col) =
                    make_float2(acc[mi][ni][0], acc[mi][ni][1]);
                *reinterpret_cast<float2*>(C + (size_t)(row + 8) * N + col) =
                    make_float2(acc[mi][ni][2], acc[mi][ni][3]);
            }
        }
    } else {
        // V: fp16 transposed into Vt[b][kvh][d][s]
#pragma unroll
        for (int mi = 0; mi < 4; ++mi) {
            int row = m0 + wm + mi * 16 + gID;
            int b0i = row >> 11, s0i = row & 2047;
            int b1i = (row + 8) >> 11, s1i = (row + 8) & 2047;
#pragma unroll
            for (int ni = 0; ni < 4; ++ni) {
                int col = n0 + wn + ni * 8 + tig * 2;
#pragma unroll
                for (int cc = 0; cc < 2; ++cc) {
                    int n = col + cc;
                    int kv = n >> 7, d = n & 127;
                    size_t base = ((size_t)(b0i * NKVH + kv) * HDIM + d) * SEQ;
                    Vt[base + s0i] = __float2half_rn(acc[mi][ni][cc]);
                    size_t base1 = ((size_t)(b1i * NKVH + kv) * HDIM + d) * SEQ;
                    Vt[base1 + s1i] = __float2half_rn(acc[mi][ni][cc + 2]);
                }
            }
        }
    }
}

__global__ __launch_bounds__(256, 2) void gemm_f16(
    const uint32_t* __restrict__ A, const uint32_t* __restrict__ B,
    float* __restrict__ C, int M, int N, int K)
{
    extern __shared__ uint32_t smem[];
    gemm_body_f16<0>(A, B, C, nullptr, M, N, K, blockIdx.x, blockIdx.y, smem);
}

__global__ __launch_bounds__(256, 2) void gemm_kv_f16(
    const uint32_t* __restrict__ A,
    const uint32_t* __restrict__ Wk, const uint32_t* __restrict__ Wv,
    float* __restrict__ Kout, __half* __restrict__ Vt,
    int M, int N, int K)
{
    extern __shared__ uint32_t smem[];
    if (blockIdx.z == 0)
        gemm_body_f16<0>(A, Wk, Kout, nullptr, M, N, K, blockIdx.x, blockIdx.y, smem);
    else
        gemm_body_f16<1>(A, Wv, nullptr, Vt, M, N, K, blockIdx.x, blockIdx.y, smem);
}

// ---------------------------------------------------------------------------
// RoPE: read fp32 g_Q/g_K, write fp16 g_Qh (pre-scaled by scale*log2e), g_Kh.
// Thread handles dims (2e, 2e+1, 2e+64, 2e+65).
// ---------------------------------------------------------------------------
__global__ void rope_kernel(const float* __restrict__ cosb,
                            const float* __restrict__ sinb)
{
    const int total = BATCH * SEQ * (NHEADS + NKVH) * 32;
    int idx = blockIdx.x * blockDim.x + threadIdx.x;
    if (idx >= total) return;
    int e    = idx & 31;
    int rest = idx >> 5;
    int slot = rest % (NHEADS + NKVH);
    int bs   = rest / (NHEADS + NKVH);
    int s    = bs % SEQ;

    const float2* cp = reinterpret_cast<const float2*>(cosb + s * HDIM);
    const float2* sp = reinterpret_cast<const float2*>(sinb + s * HDIM);
    float2 c0 = cp[e], c1 = cp[e + 32];
    float2 s0 = sp[e], s1 = sp[e + 32];

    const float2* p;
    uint32_t* o;
    float mult;
    if (slot < NHEADS) {
        p = reinterpret_cast<const float2*>(g_Q + (size_t)(bs * NHEADS + slot) * HDIM);
        o = g_Qh + (size_t)(bs * NHEADS + slot) * 64;
        mult = 0.08838834764831845f * 1.4426950408889634f;
    } else {
        p = reinterpret_cast<const float2*>(g_K + (size_t)(bs * NKVH + (slot - NHEADS)) * HDIM);
        o = g_Kh + (size_t)(bs * NKVH + (slot - NHEADS)) * 64;
        mult = 1.0f;
    }

    float2 x0 = p[e];
    float2 x1 = p[e + 32];
    float o0x = x0.x * c0.x - x1.x * s0.x;
    float o0y = x0.y * c0.y - x1.y * s0.y;
    float o1x = x1.x * c1.x + x0.x * s1.x;
    float o1y = x1.y * c1.y + x0.y * s1.y;
    o[e]      = pack2(o0x * mult, o0y * mult);
    o[e + 32] = pack2(o1x * mult, o1y * mult);
}

// ===========================================================================
// FP16 MMA flash attention: GQA-shared KV, cp.async double-buffered tiles.
// CTA = 4 heads x 32 queries (256 threads, 8 warps).
// ===========================================================================
constexpr int KSTRH = 68;    // K tile row stride (u32): (4g+t) conflict-free
constexpr int VSTRH = 20;    // Vt tile row stride:      (20g+t) conflict-free
constexpr int QSTRH = 68;
constexpr int PSTRH = 20;

constexpr int AKS0 = 0;                       // K buf 0: 32*68 = 2176
constexpr int AKS1 = AKS0 + 32 * KSTRH;       // 2176
constexpr int AVS0 = AKS1 + 32 * KSTRH;       // 4352 ; V buf: 128*20 = 2560
constexpr int AVS1 = AVS0 + 128 * VSTRH;      // 6912
constexpr int AQS  = AVS1 + 128 * VSTRH;      // 9472 ; Q: 128*68 = 8704
constexpr int APS  = AQS + 128 * QSTRH;       // 18176; P: 8*16*20 = 2560
constexpr int SMEM_ATTN = (APS + 8 * 16 * PSTRH) * 4;   // 82944 B

__global__ __launch_bounds__(256) void attn_f16_kernel()
{
    extern __shared__ uint32_t sm[];

    const int tid  = threadIdx.x;
    const int lane = tid & 31;
    const int wid  = tid >> 5;
    const int hl   = wid >> 1;
    const int sub  = wid & 1;
    const int g    = lane >> 2;
    const int t    = lane & 3;

    const int q0  = blockIdx.x * 32;
    const int kvh = blockIdx.y;
    const int b   = blockIdx.z;
    const int h   = kvh * GQA + hl;
    const int bS  = b * SEQ;
    const int qw  = q0 + sub * 16;

    const uint32_t sbase = (uint32_t)__cvta_generic_to_shared(sm);

    // ---- stage Q tiles for the 4 heads (pre-scaled fp16 from rope) ----
#pragma unroll
    for (int i = tid; i < 2048; i += 256) {       // 128 rows x 16 chunks
        int ih = i >> 9;
        int r  = (i >> 4) & 31;
        int ch = i & 15;
        const uint32_t* src = g_Qh +
            ((size_t)(bS + q0 + r) * NHEADS + kvh * GQA + ih) * 64 + ch * 4;
        cp16(sbase + (uint32_t)(AQS + (ih * 32 + r) * QSTRH + ch * 4) * 4, src);
    }
    asm volatile("cp.async.commit_group;");

    // ---- stage first K/V tile ----
    int jstart = q0 - (WIN - 1);
    if (jstart < 0) jstart = 0;
    jstart &= ~31;
    const int nt = (q0 + 32 - jstart) >> 5;

    auto stage_kv = [&](int j0, int buf) {
        const int ko = buf ? AKS1 : AKS0;
        const int vo = buf ? AVS1 : AVS0;
#pragma unroll
        for (int i = tid; i < 512; i += 256) {    // K: 32 rows x 16 chunks
            int r = i >> 4, ch = i & 15;
            const uint32_t* src = g_Kh + ((size_t)(bS + j0 + r) * NKVH + kvh) * 64 + ch * 4;
            cp16(sbase + (uint32_t)(ko + r * KSTRH + ch * 4) * 4, src);
        }
        const uint32_t* Vt = reinterpret_cast<const uint32_t*>(g_Vth) +
            ((size_t)(b * NKVH + kvh) * HDIM) * (SEQ / 2);
#pragma unroll
        for (int i = tid; i < 512; i += 256) {    // V: 128 rows x 4 chunks
            int d = i >> 2, ch = i & 3;
            const uint32_t* src = Vt + (size_t)d * (SEQ / 2) + (j0 >> 1) + ch * 4;
            cp16(sbase + (uint32_t)(vo + d * VSTRH + ch * 4) * 4, src);
        }
        asm volatile("cp.async.commit_group;");
    };

    stage_kv(jstart, 0);

    // wait for Q (and first KV is in flight); extract Q fragments
    asm volatile("cp.async.wait_group 1;");
    __syncthreads();
    uint32_t qf[8][4];
#pragma unroll
    for (int kk = 0; kk < 8; ++kk) {
        int r0 = AQS + (hl * 32 + sub * 16 + g) * QSTRH + kk * 8 + t;
        qf[kk][0] = sm[r0];
        qf[kk][1] = sm[r0 + 8 * QSTRH];
        qf[kk][2] = sm[r0 + 4];
        qf[kk][3] = sm[r0 + 8 * QSTRH + 4];
    }

    uint32_t* Pw = &sm[APS + wid * 16 * PSTRH];

    float m0r = -1e30f, m1r = -1e30f, l0 = 0.f, l1 = 0.f;
    float oacc[16][4];
#pragma unroll
    for (int ni = 0; ni < 16; ++ni)
#pragma unroll
        for (int qd = 0; qd < 4; ++qd) oacc[ni][qd] = 0.f;

    for (int it = 0; it < nt; ++it) {
        const int j0 = jstart + it * 32;
        if (it + 1 < nt) {
            stage_kv(j0 + 32, (it + 1) & 1);
            asm volatile("cp.async.wait_group 1;");
        } else {
            asm volatile("cp.async.wait_group 0;");
        }
        __syncthreads();

        const bool active = (j0 <= qw + 15) && (qw - (j0 + 31) < WIN);
        if (active) {
            const uint32_t* Ks = &sm[(it & 1) ? AKS1 : AKS0];
            const uint32_t* Vs = &sm[(it & 1) ? AVS1 : AVS0];

            // ---- QK^T ----
            float sc[4][4];
#pragma unroll
            for (int ni = 0; ni < 4; ++ni)
#pragma unroll
                for (int qd = 0; qd < 4; ++qd) sc[ni][qd] = 0.f;

#pragma unroll
            for (int kk = 0; kk < 8; ++kk) {
#pragma unroll
                for (int ni = 0; ni < 4; ++ni) {
                    uint32_t b0 = Ks[(ni * 8 + g) * KSTRH + kk * 8 + t];
                    uint32_t b1 = Ks[(ni * 8 + g) * KSTRH + kk * 8 + t + 4];
                    mma_f16(sc[ni][0], sc[ni][1], sc[ni][2], sc[ni][3],
                            qf[kk][0], qf[kk][1], qf[kk][2], qf[kk][3], b0, b1);
                }
            }

            // ---- mask + row max ----
            const int r0 = qw + g;
            float tmax0 = -1e30f, tmax1 = -1e30f;
#pragma unroll
            for (int ni = 0; ni < 4; ++ni) {
                int col0 = j0 + ni * 8 + 2 * t;
#pragma unroll
                for (int cc = 0; cc < 2; ++cc) {
                    int col = col0 + cc;
                    int d0 = r0 - col;
                    int d1 = r0 + 8 - col;
                    if (!(d0 >= 0 && d0 < WIN)) sc[ni][cc]     = -1e30f;
                    if (!(d1 >= 0 && d1 < WIN)) sc[ni][cc + 2] = -1e30f;
                    tmax0 = fmaxf(tmax0, sc[ni][cc]);
                    tmax1 = fmaxf(tmax1, sc[ni][cc + 2]);
                }
            }
            tmax0 = fmaxf(tmax0, __shfl_xor_sync(0xffffffffu, tmax0, 1));
            tmax0 = fmaxf(tmax0, __shfl_xor_sync(0xffffffffu, tmax0, 2));
            tmax1 = fmaxf(tmax1, __shfl_xor_sync(0xffffffffu, tmax1, 1));
            tmax1 = fmaxf(tmax1, __shfl_xor_sync(0xffffffffu, tmax1, 2));

            float mn0 = fmaxf(m0r, tmax0);
            float mn1 = fmaxf(m1r, tmax1);
            float cor0 = ex2(m0r - mn0);
            float cor1 = ex2(m1r - mn1);
            m0r = mn0; m1r = mn1;

            float ps0 = 0.f, ps1 = 0.f;
#pragma unroll
            for (int ni = 0; ni < 4; ++ni) {
                float p00 = (sc[ni][0] > -1e29f) ? ex2(sc[ni][0] - mn0) : 0.f;
                float p01 = (sc[ni][1] > -1e29f) ? ex2(sc[ni][1] - mn0) : 0.f;
                float p10 = (sc[ni][2] > -1e29f) ? ex2(sc[ni][2] - mn1) : 0.f;
                float p11 = (sc[ni][3] > -1e29f) ? ex2(sc[ni][3] - mn1) : 0.f;
                ps0 += p00 + p01;
                ps1 += p10 + p11;
                Pw[g * PSTRH + ni * 4 + t]       = pack2(p00, p01);
                Pw[(g + 8) * PSTRH + ni * 4 + t] = pack2(p10, p11);
            }
            ps0 += __shfl_xor_sync(0xffffffffu, ps0, 1);
            ps0 += __shfl_xor_sync(0xffffffffu, ps0, 2);
            ps1 += __shfl_xor_sync(0xffffffffu, ps1, 1);
            ps1 += __shfl_xor_sync(0xffffffffu, ps1, 2);
            l0 = l0 * cor0 + ps0;
            l1 = l1 * cor1 + ps1;

#pragma unroll
            for (int ni = 0; ni < 16; ++ni) {
                oacc[ni][0] *= cor0; oacc[ni][1] *= cor0;
                oacc[ni][2] *= cor1; oacc[ni][3] *= cor1;
            }

            __syncwarp();

            // ---- PV: out += P[16x32] * V[32x128] (V dim-major in smem) ----
#pragma unroll
            for (int kc = 0; kc < 2; ++kc) {       // two k16 steps
                uint32_t a0 = Pw[g * PSTRH + kc * 8 + t];
                uint32_t a1 = Pw[(g + 8) * PSTRH + kc * 8 + t];
                uint32_t a2 = Pw[g * PSTRH + kc * 8 + t + 4];
                uint32_t a3 = Pw[(g + 8) * PSTRH + kc * 8 + t + 4];
#pragma unroll
                for (int ni = 0; ni < 16; ++ni) {
                    uint32_t b0 = Vs[(ni * 8 + g) * VSTRH + kc * 8 + t];
                    uint32_t b1 = Vs[(ni * 8 + g) * VSTRH + kc * 8 + t + 4];
                    mma_f16(oacc[ni][0], oacc[ni][1], oacc[ni][2], oacc[ni][3],
                            a0, a1, a2, a3, b0, b1);
                }
            }
            __syncwarp();
        }
        __syncthreads();   // all warps done with this buffer before re-stage
    }

    // ---- normalize + store half2 for O-projection ----
    float inv0 = 1.f / l0;
    float inv1 = 1.f / l1;
    uint32_t* Ot  = g_AOh + ((size_t)(bS + qw + g) * NHEADS + h) * 64;
    uint32_t* Ot8 = Ot + (size_t)8 * NHEADS * 64;
#pragma unroll
    for (int ni = 0; ni < 16; ++ni) {
        Ot[ni * 4 + t]  = pack2(oacc[ni][0] * inv0, oacc[ni][1] * inv0);
        Ot8[ni * 4 + t] = pack2(oacc[ni][2] * inv1, oacc[ni][3] * inv1);
    }
}

// ---------------------------------------------------------------------------
// Launch
// ---------------------------------------------------------------------------
extern "C" void kernel_launch(void* const* d_in, const int* in_sizes, int n_in,
                              void* d_out, int out_size)
{
    const float* x    = (const float*)d_in[0];
    const float* cosb = (const float*)d_in[1];
    const float* sinb = (const float*)d_in[2];
    const float* Wq   = (const float*)d_in[3];
    const float* Wk   = (const float*)d_in[4];
    const float* Wv   = (const float*)d_in[5];
    const float* Wo   = (const float*)d_in[6];
    float* out = (float*)d_out;

    float *Q, *K;
    uint32_t *xh, *Wqh, *Wkh, *Wvh, *Woh, *AOh;
    __half* Vth;
    cudaGetSymbolAddress((void**)&Q,   g_Q);
    cudaGetSymbolAddress((void**)&K,   g_K);
    cudaGetSymbolAddress((void**)&xh,  g_xh);
    cudaGetSymbolAddress((void**)&Wqh, g_Wqh);
    cudaGetSymbolAddress((void**)&Wkh, g_Wkh);
    cudaGetSymbolAddress((void**)&Wvh, g_Wvh);
    cudaGetSymbolAddress((void**)&Woh, g_Woh);
    cudaGetSymbolAddress((void**)&AOh, g_AOh);
    cudaGetSymbolAddress((void**)&Vth, g_Vth);

    static bool attr_done = false;
    if (!attr_done) {
        cudaFuncSetAttribute(gemm_f16,    cudaFuncAttributeMaxDynamicSharedMemorySize, SMEM_GEMM);
        cudaFuncSetAttribute(gemm_kv_f16, cudaFuncAttributeMaxDynamicSharedMemorySize, SMEM_GEMM);
        cudaFuncSetAttribute(attn_f16_kernel, cudaFuncAttributeMaxDynamicSharedMemorySize, SMEM_ATTN);
        attr_done = true;
    }

    const int M = BATCH * SEQ;

    auto cvt = [](const float* s, uint32_t* d, int n) {
        int n4 = n / 4;
        cvt_h_kernel<<<(n4 + 255) / 256, 256>>>(
            reinterpret_cast<const float4*>(s), reinterpret_cast<uint2*>(d), n4);
    };
    cvt(x,  xh,  BATCH * SEQ * EMB);
    cvt(Wq, Wqh, EMB * EMB);
    cvt(Wk, Wkh, NKVH * HDIM * EMB);
    cvt(Wv, Wvh, NKVH * HDIM * EMB);
    cvt(Wo, Woh, EMB * EMB);

    // Q projection (fp32 out, rope converts)
    gemm_f16<<<dim3(EMB / 128, M / 128), 256, SMEM_GEMM>>>(xh, Wqh, Q, M, NHEADS * HDIM, EMB);
    // K (fp32 out) + V (fp16 transposed out) fused
    gemm_kv_f16<<<dim3((NKVH * HDIM) / 128, M / 128, 2), 256, SMEM_GEMM>>>(
        xh, Wkh, Wvh, K, Vth, M, NKVH * HDIM, EMB);

    {
        int total = BATCH * SEQ * (NHEADS + NKVH) * 32;
        rope_kernel<<<(total + 255) / 256, 256>>>(cosb, sinb);
    }

    attn_f16_kernel<<<dim3(SEQ / 32, NKVH, BATCH), 256, SMEM_ATTN>>>();

    // Output projection (A = attention output fp16)
    gemm_f16<<<dim3(EMB / 128, M / 128), 256, SMEM_GEMM>>>(AOh, Woh, out, M, EMB, EMB);
}